// round 11
// baseline (speedup 1.0000x reference)
#include <cuda_runtime.h>
#include <cuda_fp16.h>
#include <cstdint>

#define DINL __device__ __forceinline__

static constexpr int BATCH = 8;
static constexpr int SEQ   = 2048;
static constexpr int DIM   = 1024;
static constexpr int ODIM  = 512;

// ---------------- scratch (device globals; allocation-free) ----------------
__device__ __align__(1024) __half g_xh  [(size_t)BATCH * SEQ * DIM];    // 32 MB
__device__ __align__(1024) __half g_Wqkt[(size_t)2 * DIM * DIM];        //  4 MB [Wq^T;Wk^T]
__device__ __align__(1024) __half g_Wvt [(size_t)ODIM * DIM];           //  1 MB Wv^T [O][K]
__device__ __align__(1024) float  g_bqk [2 * DIM];                      //  8 KB packed bias
__device__ __align__(1024) __half g_QKh [(size_t)BATCH * SEQ * 2 * DIM];// 64 MB [m][Q|K]
__device__ __align__(1024) __half g_Vth [(size_t)BATCH * ODIM * SEQ];   // 16 MB V^T per batch
__device__ __align__(1024) __half g_Ph  [(size_t)BATCH * SEQ * SEQ];    // 64 MB exp-scores
__device__ __align__(1024) float  g_rsp [(size_t)BATCH * SEQ * 16];     //  1 MB rowsum partials

// ------- GEMM config: CTA 128x128, 4 warps (2x2), warp 64x64, BK=64, 3 stages -------
static constexpr int BM = 128, BN = 128, BK = 64;
static constexpr int STR  = BK + 8;                 // 72 halves/row
static constexpr int TSTG = BM * STR;               // 9216 halves per tile stage
static constexpr int NSTG = 3;
static constexpr int EXT_OFF = NSTG * 2 * TSTG * 2; // 110592 B
static constexpr int SMEM_TOTAL = EXT_OFF + 2048;   // + f32 reduce scratch

static constexpr float SCALE = 0.03125f;            // 1/sqrt(1024)

DINL void cp_async16(uint32_t smem_addr, const void* gmem) {
    asm volatile("cp.async.cg.shared.global [%0], [%1], 16;\n" :: "r"(smem_addr), "l"(gmem));
}
DINL void cp_commit() { asm volatile("cp.async.commit_group;\n"); }
DINL void cp_wait1()  { asm volatile("cp.async.wait_group 1;\n"); }

DINL void ldsm4(uint32_t* r, uint32_t addr) {
    asm volatile("ldmatrix.sync.aligned.m8n8.x4.shared.b16 {%0,%1,%2,%3}, [%4];"
                 : "=r"(r[0]), "=r"(r[1]), "=r"(r[2]), "=r"(r[3]) : "r"(addr));
}
DINL void mma16816(float* c, const uint32_t* a, uint32_t b0, uint32_t b1) {
    asm volatile(
        "mma.sync.aligned.m16n8k16.row.col.f32.f16.f16.f32 "
        "{%0,%1,%2,%3}, {%4,%5,%6,%7}, {%8,%9}, {%0,%1,%2,%3};"
        : "+f"(c[0]), "+f"(c[1]), "+f"(c[2]), "+f"(c[3])
        : "r"(a[0]), "r"(a[1]), "r"(a[2]), "r"(a[3]), "r"(b0), "r"(b1));
}

// =====================================================================
// fp16 mma.sync GEMM, C[128x128] per CTA, 4 warps (2x2), warp 64x64.
//   A: [m][k] fp16 (lda). B: K-major [n][k] fp16 (ldb)  => C = A @ B^T.
//   BIASM: 0 none, 1 bias[col], 2 bias[row]
//   TRI: 1D packed causal grid (decode bx,by from blockIdx.x, bx<=by).
//   REV: reverse by (heavy KLIM CTAs first).   KLIM: K limited to (by+1)*128.
//   OUTH: fp16 out.  EXPM: exp+mask+rowsum partials.  NORM: /rowsum.
// =====================================================================
template <int BIASM, bool TRI, bool REV, bool KLIM, bool OUTH, bool EXPM, bool NORM>
__global__ __launch_bounds__(128, 2) void gemm_h(
    const __half* __restrict__ A, const __half* __restrict__ B,
    const float* __restrict__ bias, void* __restrict__ Cv,
    int lda, int ldb, int ldc, long sAb, long sBb, long sCb, int Ktot)
{
    int bx = blockIdx.x, by = blockIdx.y;
    const int bz = blockIdx.z;
    if (TRI) {   // packed lower-triangular index -> (by, bx), bx <= by
        const int i = blockIdx.x;
        int r = (int)((sqrtf(8.f * i + 1.f) - 1.f) * 0.5f);
        while ((r + 1) * (r + 2) / 2 <= i) r++;
        while (r * (r + 1) / 2 > i) r--;
        by = r;
        bx = i - r * (r + 1) / 2;
    } else if (REV) {
        by = gridDim.y - 1 - blockIdx.y;
    }
    const int nT = (KLIM ? (by + 1) * BM : Ktot) / BK;

    A += (long)bz * sAb;
    B += (long)bz * sBb;
    const int m0 = by * BM, n0 = bx * BN;

    extern __shared__ __align__(16) char smraw[];
    __half* As = (__half*)smraw;
    __half* Bs = As + NSTG * TSTG;
    float* sext = (float*)(smraw + EXT_OFF);    // 512 f32 scratch

    const int tid = threadIdx.x, warp = tid >> 5, lane = tid & 31;
    const int wm = warp >> 1, wn = warp & 1;    // 2x2 warps, 64x64 warp tile

    if (NORM) {                                  // 1/rowsum for this CTA's 128 rows
        const int q = m0 + tid;
        const float* rp = g_rsp + ((long)bz * SEQ + q) * 16;
        float s = 0.f;
        const int pm = q >> 7;                   // last 128-wide key tile for row q
        for (int p = 0; p <= pm; p++) s += rp[p];
        sext[tid] = 1.f / s;
        __syncthreads();
    }

    auto load = [&](int stage, int t) {
        __half* da = As + stage * TSTG;
        __half* db = Bs + stage * TSTG;
#pragma unroll
        for (int i = 0; i < 8; i++) {           // 128 rows x 8 chunks of 8 halves
            const int j = i * 128 + tid;
            const int r = j >> 3, c = (j & 7) << 3;
            cp_async16((uint32_t)__cvta_generic_to_shared(da + r * STR + c),
                       A + (long)(m0 + r) * lda + t * BK + c);
            cp_async16((uint32_t)__cvta_generic_to_shared(db + r * STR + c),
                       B + (long)(n0 + r) * ldb + t * BK + c);
        }
    };

    float acc[4][8][4];
#pragma unroll
    for (int i = 0; i < 4; i++)
#pragma unroll
        for (int j = 0; j < 8; j++)
#pragma unroll
            for (int k = 0; k < 4; k++) acc[i][j][k] = 0.f;

    load(0, 0); cp_commit();
    load(1, 1); cp_commit();

    const uint32_t aB = (uint32_t)__cvta_generic_to_shared(As) +
        ((((wm * 64 + (lane & 15)) * STR) + ((lane >> 4) << 3)) << 1);
    const uint32_t bB = (uint32_t)__cvta_generic_to_shared(Bs) +
        ((((wn * 64 + (lane & 15)) * STR) + ((lane >> 4) << 3)) << 1);

    uint32_t a[2][4][4], b[2][4][4];            // double-buffered fragments
    int st = 0;
    for (int t = 0; t < nT; t++) {
        cp_wait1();                              // stage t resident
        __syncthreads();
        if (t + 2 < nT) load(st == 0 ? 2 : st - 1, t + 2);
        cp_commit();                             // uniform group count (may be empty)

        const uint32_t aS = aB + st * (TSTG * 2);
        const uint32_t bS = bB + st * (TSTG * 2);

        // prime ks=0 fragments
#pragma unroll
        for (int mt = 0; mt < 4; mt++) ldsm4(a[0][mt], aS + mt * (16 * STR * 2));
#pragma unroll
        for (int gb = 0; gb < 4; gb++) ldsm4(b[0][gb], bS + gb * (16 * STR * 2));

#pragma unroll
        for (int ks = 0; ks < 4; ks++) {         // 4 x k16 per 64-deep stage
            const int cur = ks & 1, nxt = cur ^ 1;
            if (ks < 3) {                        // prefetch next fragments under MMAs
#pragma unroll
                for (int mt = 0; mt < 4; mt++)
                    ldsm4(a[nxt][mt], aS + mt * (16 * STR * 2) + (ks + 1) * 32);
#pragma unroll
                for (int gb = 0; gb < 4; gb++)
                    ldsm4(b[nxt][gb], bS + gb * (16 * STR * 2) + (ks + 1) * 32);
            }
#pragma unroll
            for (int mt = 0; mt < 4; mt++)
#pragma unroll
                for (int nt = 0; nt < 8; nt++)
                    mma16816(acc[mt][nt], a[cur][mt],
                             b[cur][nt >> 1][nt & 1], b[cur][nt >> 1][(nt & 1) + 2]);
        }
        st = (st == 2) ? 0 : st + 1;
    }
    __syncthreads();                             // before epilogue smem reuse

    // ---- epilogue ----
    const int g = lane >> 2, cth = lane & 3;
    float rsum[8];
#pragma unroll
    for (int i = 0; i < 8; i++) rsum[i] = 0.f;

#pragma unroll
    for (int mt = 0; mt < 4; mt++) {
        const int lr = wm * 64 + mt * 16 + g;
        const int rr = m0 + lr;
        float rb0 = 0.f, rb1 = 0.f;
        if (BIASM == 2) { rb0 = __ldg(bias + rr); rb1 = __ldg(bias + rr + 8); }
        float inv0 = 1.f, inv1 = 1.f;
        if (NORM) { inv0 = sext[lr]; inv1 = sext[lr + 8]; }
#pragma unroll
        for (int nt = 0; nt < 8; nt++) {
            const int cc = n0 + wn * 64 + nt * 8 + (cth << 1);
            float b0 = 0.f, b1 = 0.f;
            if (BIASM == 1) { b0 = __ldg(bias + cc); b1 = __ldg(bias + cc + 1); }
            float v00 = acc[mt][nt][0] + (BIASM == 2 ? rb0 : b0);
            float v01 = acc[mt][nt][1] + (BIASM == 2 ? rb0 : b1);
            float v10 = acc[mt][nt][2] + (BIASM == 2 ? rb1 : b0);
            float v11 = acc[mt][nt][3] + (BIASM == 2 ? rb1 : b1);
            if (EXPM) {   // causal mask + exp (max-free: |s*scale| ~ O(2))
                v00 = (cc     <= rr    ) ? __expf(v00 * SCALE) : 0.f;
                v01 = (cc + 1 <= rr    ) ? __expf(v01 * SCALE) : 0.f;
                v10 = (cc     <= rr + 8) ? __expf(v10 * SCALE) : 0.f;
                v11 = (cc + 1 <= rr + 8) ? __expf(v11 * SCALE) : 0.f;
                rsum[mt * 2]     += v00 + v01;
                rsum[mt * 2 + 1] += v10 + v11;
            }
            if (NORM) { v00 *= inv0; v01 *= inv0; v10 *= inv1; v11 *= inv1; }
            if (OUTH) {
                __half* C = (__half*)Cv + (long)bz * sCb;
                *(__half2*)(C + (long)rr * ldc + cc)       = __floats2half2_rn(v00, v01);
                *(__half2*)(C + (long)(rr + 8) * ldc + cc) = __floats2half2_rn(v10, v11);
            } else {
                float* C = (float*)Cv + (long)bz * sCb;
                *(float2*)(C + (long)rr * ldc + cc)       = make_float2(v00, v01);
                *(float2*)(C + (long)(rr + 8) * ldc + cc) = make_float2(v10, v11);
            }
        }
    }

    if (EXPM) {   // deterministic rowsum partials: quad shfl -> smem -> global
#pragma unroll
        for (int i = 0; i < 8; i++) {
            rsum[i] += __shfl_xor_sync(0xffffffffu, rsum[i], 1);
            rsum[i] += __shfl_xor_sync(0xffffffffu, rsum[i], 2);
        }
        if (cth == 0) {
#pragma unroll
            for (int mt = 0; mt < 4; mt++) {
                sext[wn * BM + wm * 64 + mt * 16 + g]     = rsum[mt * 2];
                sext[wn * BM + wm * 64 + mt * 16 + g + 8] = rsum[mt * 2 + 1];
            }
        }
        __syncthreads();
        const float s = sext[tid] + sext[BM + tid];   // 2 warp-columns
        g_rsp[((long)bz * SEQ + m0 + tid) * 16 + bx] = s;
    }
}

// ---------------- prep kernels (2 launches total) ----------------
__global__ __launch_bounds__(256) void k_f2h(const float4* __restrict__ in,
                                             __half2* __restrict__ out, int n4)
{
    const int i = blockIdx.x * blockDim.x + threadIdx.x;
    if (i < n4) {
        const float4 v = in[i];
        out[2 * i]     = __floats2half2_rn(v.x, v.y);
        out[2 * i + 1] = __floats2half2_rn(v.z, v.w);
    }
}

// One launch: Wq^T -> Wqkt[0:1024], Wk^T -> Wqkt[1024:2048], Wv^T -> Wvt,
// and packed bias bqk = [bq|bk]. grid (32, 32, 3); z=2 uses x-blocks 16..31 for bias.
__global__ __launch_bounds__(256) void k_prep_w(
    const float* __restrict__ Wq, const float* __restrict__ Wk,
    const float* __restrict__ Wv, const float* __restrict__ bq,
    const float* __restrict__ bk)
{
    const int z = blockIdx.z;
    if (z == 2 && blockIdx.x >= 16) {           // bias pack on spare blocks
        const int i = (blockIdx.x - 16) * 256 + (threadIdx.y * 32 + threadIdx.x);
        if (i < 2 * DIM) g_bqk[i] = (i < DIM) ? bq[i] : bk[i - DIM];
        return;
    }
    const float* W = (z == 0) ? Wq : (z == 1) ? Wk : Wv;
    __half* Wt     = (z == 2) ? g_Wvt : g_Wqkt;
    const int N    = (z == 2) ? ODIM : DIM;
    const int roff = (z == 1) ? DIM : 0;

    __shared__ float t[32][33];
    const int n0 = blockIdx.x * 32, k0 = blockIdx.y * 32;
    const int x = threadIdx.x, y = threadIdx.y;   // 32 x 8
#pragma unroll
    for (int r = 0; r < 32; r += 8) t[y + r][x] = W[(long)(k0 + y + r) * N + n0 + x];
    __syncthreads();
#pragma unroll
    for (int r = 0; r < 32; r += 8)
        Wt[(long)(roff + n0 + y + r) * DIM + k0 + x] = __float2half(t[x][y + r]);
}

// ---------------- host side ----------------
extern "C" void kernel_launch(void* const* d_in, const int* in_sizes, int n_in,
                              void* d_out, int out_size)
{
    (void)in_sizes; (void)n_in; (void)out_size;
    const float* x  = (const float*)d_in[0];
    const float* Wq = (const float*)d_in[1];
    const float* bq = (const float*)d_in[2];
    const float* Wk = (const float*)d_in[3];
    const float* bk = (const float*)d_in[4];
    const float* Wv = (const float*)d_in[5];
    const float* bv = (const float*)d_in[6];
    float* out = (float*)d_out;

    __half *xh, *Wqkt, *Wvt, *QKh, *Vth, *Ph;
    float* bqk;
    cudaGetSymbolAddress((void**)&xh,   g_xh);
    cudaGetSymbolAddress((void**)&Wqkt, g_Wqkt);
    cudaGetSymbolAddress((void**)&Wvt,  g_Wvt);
    cudaGetSymbolAddress((void**)&bqk,  g_bqk);
    cudaGetSymbolAddress((void**)&QKh,  g_QKh);
    cudaGetSymbolAddress((void**)&Vth,  g_Vth);
    cudaGetSymbolAddress((void**)&Ph,   g_Ph);

    cudaFuncSetAttribute(gemm_h<1, false, false, false, true, false, false>,
                         cudaFuncAttributeMaxDynamicSharedMemorySize, SMEM_TOTAL);
    cudaFuncSetAttribute(gemm_h<2, false, false, false, true, false, false>,
                         cudaFuncAttributeMaxDynamicSharedMemorySize, SMEM_TOTAL);
    cudaFuncSetAttribute(gemm_h<0, true, false, false, true, true, false>,
                         cudaFuncAttributeMaxDynamicSharedMemorySize, SMEM_TOTAL);
    cudaFuncSetAttribute(gemm_h<0, false, true, true, false, false, true>,
                         cudaFuncAttributeMaxDynamicSharedMemorySize, SMEM_TOTAL);

    const dim3 thr(128);
    const int MTOT = BATCH * SEQ;   // 16384

    // ---- prep (2 launches) ----
    k_f2h<<<(MTOT * DIM / 4 + 255) / 256, 256>>>((const float4*)x, (__half2*)xh, MTOT * DIM / 4);
    k_prep_w<<<dim3(32, 32, 3), dim3(32, 8)>>>(Wq, Wk, Wv, bq, bk);

    // ---- QK = xh @ [Wqt|Wkt]^T + bqk  [16384 x 2048], fp16 out ----
    gemm_h<1, false, false, false, true, false, false>
        <<<dim3(2 * DIM / BN, MTOT / BM, 1), thr, SMEM_TOTAL>>>(
        xh, Wqkt, bqk, QKh, DIM, DIM, 2 * DIM, 0, 0, 0, DIM);
    // ---- Ph[b] = exp(scale * Q[b] @ K[b]^T), packed causal grid + rowsum partials ----
    gemm_h<0, true, false, false, true, true, false>
        <<<dim3(136, 1, BATCH), thr, SMEM_TOTAL>>>(
        QKh, QKh + DIM, nullptr, Ph, 2 * DIM, 2 * DIM, SEQ,
        (long)SEQ * 2 * DIM, (long)SEQ * 2 * DIM, (long)SEQ * SEQ, DIM);
    // ---- V^T[b] = Wvt @ xh[b]^T + bv[row]  [512 x 2048] per batch, fp16 out ----
    gemm_h<2, false, false, false, true, false, false>
        <<<dim3(SEQ / BN, ODIM / BM, BATCH), thr, SMEM_TOTAL>>>(
        Wvt, xh, bv, Vth, DIM, DIM, SEQ, 0, (long)SEQ * DIM, (long)ODIM * SEQ, DIM);
    // ---- out[b] = (Ph[b] @ Vth[b]^T) / rowsum, heavy CTAs first ----
    gemm_h<0, false, true, true, false, false, true>
        <<<dim3(ODIM / BN, SEQ / BM, BATCH), thr, SMEM_TOTAL>>>(
        Ph, Vth, nullptr, out, SEQ, SEQ, ODIM,
        (long)SEQ * SEQ, (long)ODIM * SEQ, (long)SEQ * ODIM, SEQ);
}

// round 12
// speedup vs baseline: 1.0803x; 1.0803x over previous
#include <cuda_runtime.h>
#include <cuda_fp16.h>
#include <cstdint>

#define DINL __device__ __forceinline__

static constexpr int BATCH = 8;
static constexpr int SEQ   = 2048;
static constexpr int DIM   = 1024;
static constexpr int ODIM  = 512;

// ---------------- scratch (device globals; allocation-free) ----------------
__device__ __align__(1024) __half g_xh  [(size_t)BATCH * SEQ * DIM];    // 32 MB
__device__ __align__(1024) __half g_Wqkt[(size_t)2 * DIM * DIM];        //  4 MB [Wq^T;Wk^T]
__device__ __align__(1024) __half g_Wvt [(size_t)ODIM * DIM];           //  1 MB Wv^T [O][K]
__device__ __align__(1024) float  g_bqk [2 * DIM];                      //  8 KB packed bias
__device__ __align__(1024) __half g_QKh [(size_t)BATCH * SEQ * 2 * DIM];// 64 MB [m][Q|K]
__device__ __align__(1024) __half g_Vth [(size_t)BATCH * ODIM * SEQ];   // 16 MB V^T per batch
__device__ __align__(1024) __half g_Ph  [(size_t)BATCH * SEQ * SEQ];    // 64 MB exp-scores
__device__ __align__(1024) float  g_rsp [(size_t)BATCH * SEQ * 16];     //  1 MB rowsum partials

// ------- GEMM config: CTA 128x128, 4 warps (2x2), warp 64x64, BK=64, 3 stages -------
static constexpr int BM = 128, BN = 128, BK = 64;
static constexpr int STR  = BK + 8;                 // 72 halves/row
static constexpr int TSTG = BM * STR;               // 9216 halves per tile stage
static constexpr int NSTG = 3;
static constexpr int EXT_OFF = NSTG * 2 * TSTG * 2; // 110592 B
static constexpr int SMEM_TOTAL = EXT_OFF + 2048;   // + f32 reduce scratch

static constexpr float SCALE = 0.03125f;            // 1/sqrt(1024)

DINL void cp_async16(uint32_t smem_addr, const void* gmem) {
    asm volatile("cp.async.cg.shared.global [%0], [%1], 16;\n" :: "r"(smem_addr), "l"(gmem));
}
DINL void cp_commit() { asm volatile("cp.async.commit_group;\n"); }
DINL void cp_wait1()  { asm volatile("cp.async.wait_group 1;\n"); }

DINL void ldsm4(uint32_t* r, uint32_t addr) {
    asm volatile("ldmatrix.sync.aligned.m8n8.x4.shared.b16 {%0,%1,%2,%3}, [%4];"
                 : "=r"(r[0]), "=r"(r[1]), "=r"(r[2]), "=r"(r[3]) : "r"(addr));
}
DINL void mma16816(float* c, const uint32_t* a, uint32_t b0, uint32_t b1) {
    asm volatile(
        "mma.sync.aligned.m16n8k16.row.col.f32.f16.f16.f32 "
        "{%0,%1,%2,%3}, {%4,%5,%6,%7}, {%8,%9}, {%0,%1,%2,%3};"
        : "+f"(c[0]), "+f"(c[1]), "+f"(c[2]), "+f"(c[3])
        : "r"(a[0]), "r"(a[1]), "r"(a[2]), "r"(a[3]), "r"(b0), "r"(b1));
}

// ---------------- shared mainloop (CTA 128x128, 4 warps 2x2, warp 64x64) ----------------
// Computes acc = A[m0:m0+128, :K] @ B[n0:n0+128, :K]^T with fp16 operands.
struct MainloopOut { float acc[4][8][4]; };

template <typename F>
DINL void run_mainloop(const __half* __restrict__ A, const __half* __restrict__ B,
                       int lda, int ldb, int m0, int n0, int nT,
                       char* smraw, int tid, int wm, int wn, int lane, float (*acc)[8][4])
{
    __half* As = (__half*)smraw;
    __half* Bs = As + NSTG * TSTG;

    auto load = [&](int stage, int t) {
        __half* da = As + stage * TSTG;
        __half* db = Bs + stage * TSTG;
#pragma unroll
        for (int i = 0; i < 8; i++) {
            const int j = i * 128 + tid;
            const int r = j >> 3, c = (j & 7) << 3;
            cp_async16((uint32_t)__cvta_generic_to_shared(da + r * STR + c),
                       A + (long)(m0 + r) * lda + t * BK + c);
            cp_async16((uint32_t)__cvta_generic_to_shared(db + r * STR + c),
                       B + (long)(n0 + r) * ldb + t * BK + c);
        }
    };

    load(0, 0); cp_commit();
    load(1, 1); cp_commit();

    const uint32_t aB = (uint32_t)__cvta_generic_to_shared(As) +
        ((((wm * 64 + (lane & 15)) * STR) + ((lane >> 4) << 3)) << 1);
    const uint32_t bB = (uint32_t)__cvta_generic_to_shared(Bs) +
        ((((wn * 64 + (lane & 15)) * STR) + ((lane >> 4) << 3)) << 1);

    uint32_t a[2][4][4], b[2][4][4];
    int st = 0;
    for (int t = 0; t < nT; t++) {
        cp_wait1();
        __syncthreads();
        if (t + 2 < nT) load(st == 0 ? 2 : st - 1, t + 2);
        cp_commit();

        const uint32_t aS = aB + st * (TSTG * 2);
        const uint32_t bS = bB + st * (TSTG * 2);

#pragma unroll
        for (int mt = 0; mt < 4; mt++) ldsm4(a[0][mt], aS + mt * (16 * STR * 2));
#pragma unroll
        for (int gb = 0; gb < 4; gb++) ldsm4(b[0][gb], bS + gb * (16 * STR * 2));

#pragma unroll
        for (int ks = 0; ks < 4; ks++) {
            const int cur = ks & 1, nxt = cur ^ 1;
            if (ks < 3) {
#pragma unroll
                for (int mt = 0; mt < 4; mt++)
                    ldsm4(a[nxt][mt], aS + mt * (16 * STR * 2) + (ks + 1) * 32);
#pragma unroll
                for (int gb = 0; gb < 4; gb++)
                    ldsm4(b[nxt][gb], bS + gb * (16 * STR * 2) + (ks + 1) * 32);
            }
#pragma unroll
            for (int mt = 0; mt < 4; mt++)
#pragma unroll
                for (int nt = 0; nt < 8; nt++)
                    mma16816(acc[mt][nt], a[cur][mt],
                             b[cur][nt >> 1][nt & 1], b[cur][nt >> 1][(nt & 1) + 2]);
        }
        st = (st == 2) ? 0 : st + 1;
    }
    __syncthreads();
}
template <typename T> struct Tag {};

// =====================================================================
// Templated GEMM (used for QKproj and PV).
// =====================================================================
template <int BIASM, bool KLIM, bool OUTH, bool NORM>
__global__ __launch_bounds__(128, 2) void gemm_h(
    const __half* __restrict__ A, const __half* __restrict__ B,
    const float* __restrict__ bias, void* __restrict__ Cv,
    int lda, int ldb, int ldc, long sAb, long sBb, long sCb, int Ktot)
{
    const int bx = blockIdx.x, by = blockIdx.y, bz = blockIdx.z;
    const int nT = (KLIM ? (by + 1) * BM : Ktot) / BK;

    A += (long)bz * sAb;
    B += (long)bz * sBb;
    const int m0 = by * BM, n0 = bx * BN;

    extern __shared__ __align__(16) char smraw[];
    float* sext = (float*)(smraw + EXT_OFF);

    const int tid = threadIdx.x, warp = tid >> 5, lane = tid & 31;
    const int wm = warp >> 1, wn = warp & 1;

    if (NORM) {
        const int q = m0 + tid;
        const float* rp = g_rsp + ((long)bz * SEQ + q) * 16;
        float s = 0.f;
        const int pm = q >> 7;
        for (int p = 0; p <= pm; p++) s += rp[p];
        sext[tid] = 1.f / s;
        __syncthreads();
    }

    float acc[4][8][4];
#pragma unroll
    for (int i = 0; i < 4; i++)
#pragma unroll
        for (int j = 0; j < 8; j++)
#pragma unroll
            for (int k = 0; k < 4; k++) acc[i][j][k] = 0.f;

    run_mainloop<Tag<void>>(A, B, lda, ldb, m0, n0, nT, smraw, tid, wm, wn, lane, acc);

    const int g = lane >> 2, cth = lane & 3;
#pragma unroll
    for (int mt = 0; mt < 4; mt++) {
        const int lr = wm * 64 + mt * 16 + g;
        const int rr = m0 + lr;
        float rb0 = 0.f, rb1 = 0.f;
        if (BIASM == 2) { rb0 = __ldg(bias + rr); rb1 = __ldg(bias + rr + 8); }
        float inv0 = 1.f, inv1 = 1.f;
        if (NORM) { inv0 = sext[lr]; inv1 = sext[lr + 8]; }
#pragma unroll
        for (int nt = 0; nt < 8; nt++) {
            const int cc = n0 + wn * 64 + nt * 8 + (cth << 1);
            float b0 = 0.f, b1 = 0.f;
            if (BIASM == 1) { b0 = __ldg(bias + cc); b1 = __ldg(bias + cc + 1); }
            float v00 = acc[mt][nt][0] + (BIASM == 2 ? rb0 : b0);
            float v01 = acc[mt][nt][1] + (BIASM == 2 ? rb0 : b1);
            float v10 = acc[mt][nt][2] + (BIASM == 2 ? rb1 : b0);
            float v11 = acc[mt][nt][3] + (BIASM == 2 ? rb1 : b1);
            if (NORM) { v00 *= inv0; v01 *= inv0; v10 *= inv1; v11 *= inv1; }
            if (OUTH) {
                __half* C = (__half*)Cv + (long)bz * sCb;
                *(__half2*)(C + (long)rr * ldc + cc)       = __floats2half2_rn(v00, v01);
                *(__half2*)(C + (long)(rr + 8) * ldc + cc) = __floats2half2_rn(v10, v11);
            } else {
                float* C = (float*)Cv + (long)bz * sCb;
                *(float2*)(C + (long)rr * ldc + cc)       = make_float2(v00, v01);
                *(float2*)(C + (long)(rr + 8) * ldc + cc) = make_float2(v10, v11);
            }
        }
    }
}

// =====================================================================
// Fused phase-2 kernel: QKT (exp+mask+rowsum) CTAs and Vproj CTAs in ONE
// launch, so SMs interleave their stalls. grid (136 + 64, 1, BATCH).
// =====================================================================
__global__ __launch_bounds__(128, 2) void k_p2(const float* __restrict__ bv)
{
    const int bz = blockIdx.z;
    const bool qkt = blockIdx.x < 136;
    int bx, by, lda, ldb, ldc;
    const __half *A, *B;
    __half* C;

    if (qkt) {   // packed lower-triangular index -> (by, bx), bx <= by
        const int i = blockIdx.x;
        int r = (int)((sqrtf(8.f * i + 1.f) - 1.f) * 0.5f);
        while ((r + 1) * (r + 2) / 2 <= i) r++;
        while (r * (r + 1) / 2 > i) r--;
        by = r;
        bx = i - r * (r + 1) / 2;
        A = g_QKh + (long)bz * SEQ * 2 * DIM;          // Q rows
        B = g_QKh + (long)bz * SEQ * 2 * DIM + DIM;    // K rows
        lda = ldb = 2 * DIM;
        C = g_Ph + (long)bz * SEQ * SEQ;
        ldc = SEQ;
    } else {     // Vproj tile: V^T[b] = Wvt @ xh[b]^T + bv[row]
        const int j = blockIdx.x - 136;                 // 0..63
        bx = j & 15;                                    // seq tile (n)
        by = j >> 4;                                    // odim tile (m), 0..3
        A = g_Wvt;
        lda = DIM;
        B = g_xh + (long)bz * SEQ * DIM;
        ldb = DIM;
        C = g_Vth + (long)bz * ODIM * SEQ;
        ldc = SEQ;
    }
    const int m0 = by * BM, n0 = bx * BN;
    const int nT = DIM / BK;   // 16 for both modes

    extern __shared__ __align__(16) char smraw[];
    float* sext = (float*)(smraw + EXT_OFF);

    const int tid = threadIdx.x, warp = tid >> 5, lane = tid & 31;
    const int wm = warp >> 1, wn = warp & 1;

    float acc[4][8][4];
#pragma unroll
    for (int i = 0; i < 4; i++)
#pragma unroll
        for (int j = 0; j < 8; j++)
#pragma unroll
            for (int k = 0; k < 4; k++) acc[i][j][k] = 0.f;

    run_mainloop<Tag<void>>(A, B, lda, ldb, m0, n0, nT, smraw, tid, wm, wn, lane, acc);

    // ---- epilogue (runtime mode) ----
    const int g = lane >> 2, cth = lane & 3;
    float rsum[8];
#pragma unroll
    for (int i = 0; i < 8; i++) rsum[i] = 0.f;

#pragma unroll
    for (int mt = 0; mt < 4; mt++) {
        const int lr = wm * 64 + mt * 16 + g;
        const int rr = m0 + lr;
        float rb0 = 0.f, rb1 = 0.f;
        if (!qkt) { rb0 = __ldg(bv + rr); rb1 = __ldg(bv + rr + 8); }
#pragma unroll
        for (int nt = 0; nt < 8; nt++) {
            const int cc = n0 + wn * 64 + nt * 8 + (cth << 1);
            float v00 = acc[mt][nt][0] + rb0;
            float v01 = acc[mt][nt][1] + rb0;
            float v10 = acc[mt][nt][2] + rb1;
            float v11 = acc[mt][nt][3] + rb1;
            if (qkt) {   // causal mask + exp (max-free: |s*scale| ~ O(2))
                v00 = (cc     <= rr    ) ? __expf(v00 * SCALE) : 0.f;
                v01 = (cc + 1 <= rr    ) ? __expf(v01 * SCALE) : 0.f;
                v10 = (cc     <= rr + 8) ? __expf(v10 * SCALE) : 0.f;
                v11 = (cc + 1 <= rr + 8) ? __expf(v11 * SCALE) : 0.f;
                rsum[mt * 2]     += v00 + v01;
                rsum[mt * 2 + 1] += v10 + v11;
            }
            *(__half2*)(C + (long)rr * ldc + cc)       = __floats2half2_rn(v00, v01);
            *(__half2*)(C + (long)(rr + 8) * ldc + cc) = __floats2half2_rn(v10, v11);
        }
    }

    if (qkt) {   // deterministic rowsum partials: quad shfl -> smem -> global
#pragma unroll
        for (int i = 0; i < 8; i++) {
            rsum[i] += __shfl_xor_sync(0xffffffffu, rsum[i], 1);
            rsum[i] += __shfl_xor_sync(0xffffffffu, rsum[i], 2);
        }
        if (cth == 0) {
#pragma unroll
            for (int mt = 0; mt < 4; mt++) {
                sext[wn * BM + wm * 64 + mt * 16 + g]     = rsum[mt * 2];
                sext[wn * BM + wm * 64 + mt * 16 + g + 8] = rsum[mt * 2 + 1];
            }
        }
        __syncthreads();
        const float s = sext[tid] + sext[BM + tid];
        g_rsp[((long)bz * SEQ + m0 + tid) * 16 + bx] = s;
    }
}

// ---------------- prep kernels (2 launches total) ----------------
__global__ __launch_bounds__(256) void k_f2h(const float4* __restrict__ in,
                                             __half2* __restrict__ out, int n4)
{
    const int i = blockIdx.x * blockDim.x + threadIdx.x;
    if (i < n4) {
        const float4 v = in[i];
        out[2 * i]     = __floats2half2_rn(v.x, v.y);
        out[2 * i + 1] = __floats2half2_rn(v.z, v.w);
    }
}

// One launch: Wq^T, Wk^T -> Wqkt, Wv^T -> Wvt, bias pack.
__global__ __launch_bounds__(256) void k_prep_w(
    const float* __restrict__ Wq, const float* __restrict__ Wk,
    const float* __restrict__ Wv, const float* __restrict__ bq,
    const float* __restrict__ bk)
{
    const int z = blockIdx.z;
    if (z == 2 && blockIdx.x >= 16) {           // bias pack on spare blocks
        const int i = (blockIdx.x - 16) * 256 + (threadIdx.y * 32 + threadIdx.x);
        if (i < 2 * DIM) g_bqk[i] = (i < DIM) ? bq[i] : bk[i - DIM];
        return;
    }
    const float* W = (z == 0) ? Wq : (z == 1) ? Wk : Wv;
    __half* Wt     = (z == 2) ? g_Wvt : g_Wqkt;
    const int N    = (z == 2) ? ODIM : DIM;
    const int roff = (z == 1) ? DIM : 0;

    __shared__ float t[32][33];
    const int n0 = blockIdx.x * 32, k0 = blockIdx.y * 32;
    const int x = threadIdx.x, y = threadIdx.y;
#pragma unroll
    for (int r = 0; r < 32; r += 8) t[y + r][x] = W[(long)(k0 + y + r) * N + n0 + x];
    __syncthreads();
#pragma unroll
    for (int r = 0; r < 32; r += 8)
        Wt[(long)(roff + n0 + y + r) * DIM + k0 + x] = __float2half(t[x][y + r]);
}

// ---------------- host side ----------------
extern "C" void kernel_launch(void* const* d_in, const int* in_sizes, int n_in,
                              void* d_out, int out_size)
{
    (void)in_sizes; (void)n_in; (void)out_size;
    const float* x  = (const float*)d_in[0];
    const float* Wq = (const float*)d_in[1];
    const float* bq = (const float*)d_in[2];
    const float* Wk = (const float*)d_in[3];
    const float* bk = (const float*)d_in[4];
    const float* Wv = (const float*)d_in[5];
    const float* bv = (const float*)d_in[6];
    float* out = (float*)d_out;

    __half *xh, *Wqkt, *QKh, *Vth, *Ph;
    float* bqk;
    cudaGetSymbolAddress((void**)&xh,   g_xh);
    cudaGetSymbolAddress((void**)&Wqkt, g_Wqkt);
    cudaGetSymbolAddress((void**)&bqk,  g_bqk);
    cudaGetSymbolAddress((void**)&QKh,  g_QKh);
    cudaGetSymbolAddress((void**)&Vth,  g_Vth);
    cudaGetSymbolAddress((void**)&Ph,   g_Ph);

    cudaFuncSetAttribute(gemm_h<1, false, true, false>,
                         cudaFuncAttributeMaxDynamicSharedMemorySize, SMEM_TOTAL);
    cudaFuncSetAttribute(k_p2,
                         cudaFuncAttributeMaxDynamicSharedMemorySize, SMEM_TOTAL);
    cudaFuncSetAttribute(gemm_h<0, true, false, true>,
                         cudaFuncAttributeMaxDynamicSharedMemorySize, SMEM_TOTAL);

    const dim3 thr(128);
    const int MTOT = BATCH * SEQ;   // 16384

    // ---- prep (2 launches) ----
    k_f2h<<<(MTOT * DIM / 4 + 255) / 256, 256>>>((const float4*)x, (__half2*)xh, MTOT * DIM / 4);
    k_prep_w<<<dim3(32, 32, 3), dim3(32, 8)>>>(Wq, Wk, Wv, bq, bk);

    // ---- QK = xh @ [Wqt|Wkt]^T + bqk  [16384 x 2048], fp16 out ----
    gemm_h<1, false, true, false>
        <<<dim3(2 * DIM / BN, MTOT / BM, 1), thr, SMEM_TOTAL>>>(
        xh, Wqkt, bqk, QKh, DIM, DIM, 2 * DIM, 0, 0, 0, DIM);

    // ---- fused phase 2: QKT (exp-scores + rowsums) AND Vproj, one launch ----
    k_p2<<<dim3(136 + 64, 1, BATCH), thr, SMEM_TOTAL>>>(bv);

    // ---- out[b] = (Ph[b] @ Vth[b]^T) / rowsum  (K causally limited) ----
    gemm_h<0, true, false, true>
        <<<dim3(ODIM / BN, SEQ / BM, BATCH), thr, SMEM_TOTAL>>>(
        Ph, Vth, nullptr, out, SEQ, SEQ, ODIM,
        (long)SEQ * SEQ, (long)ODIM * SEQ, (long)SEQ * ODIM, SEQ);
}

// round 13
// speedup vs baseline: 1.0853x; 1.0047x over previous
#include <cuda_runtime.h>
#include <cuda_fp16.h>
#include <cstdint>

#define DINL __device__ __forceinline__

static constexpr int BATCH = 8;
static constexpr int SEQ   = 2048;
static constexpr int DIM   = 1024;
static constexpr int ODIM  = 512;

// ---------------- scratch (device globals; allocation-free) ----------------
__device__ __align__(1024) __half g_xh  [(size_t)BATCH * SEQ * DIM];    // 32 MB
__device__ __align__(1024) __half g_Wqkt[(size_t)2 * DIM * DIM];        //  4 MB [Wq^T;Wk^T]
__device__ __align__(1024) __half g_Wvt [(size_t)ODIM * DIM];           //  1 MB Wv^T [O][K]
__device__ __align__(1024) float  g_bqk [2 * DIM];                      //  8 KB packed bias
__device__ __align__(1024) __half g_QKh [(size_t)BATCH * SEQ * 2 * DIM];// 64 MB [m][Q|K]
__device__ __align__(1024) __half g_Vth [(size_t)BATCH * ODIM * SEQ];   // 16 MB V^T per batch
__device__ __align__(1024) __half g_Ph  [(size_t)BATCH * SEQ * SEQ];    // 64 MB exp-scores
__device__ __align__(1024) float  g_rsp [(size_t)BATCH * SEQ * 16];     //  1 MB rowsum partials

// ------- GEMM config: CTA 128x128, 4 warps (2x2), warp 64x64, BK=64, 3 stages -------
static constexpr int BM = 128, BN = 128, BK = 64;
static constexpr int STR  = BK + 8;                 // 72 halves/row
static constexpr int TSTG = BM * STR;               // 9216 halves per tile stage
static constexpr int NSTG = 3;
static constexpr int EXT_OFF = NSTG * 2 * TSTG * 2; // 110592 B
static constexpr int SMEM_TOTAL = EXT_OFF + 2048;   // + f32 reduce scratch

static constexpr float SCALE = 0.03125f;            // 1/sqrt(1024)

DINL void cp_async16(uint32_t smem_addr, const void* gmem) {
    asm volatile("cp.async.cg.shared.global [%0], [%1], 16;\n" :: "r"(smem_addr), "l"(gmem));
}
DINL void cp_commit() { asm volatile("cp.async.commit_group;\n"); }
DINL void cp_wait1()  { asm volatile("cp.async.wait_group 1;\n"); }

DINL void ldsm4(uint32_t* r, uint32_t addr) {
    asm volatile("ldmatrix.sync.aligned.m8n8.x4.shared.b16 {%0,%1,%2,%3}, [%4];"
                 : "=r"(r[0]), "=r"(r[1]), "=r"(r[2]), "=r"(r[3]) : "r"(addr));
}
DINL void mma16816(float* c, const uint32_t* a, uint32_t b0, uint32_t b1) {
    asm volatile(
        "mma.sync.aligned.m16n8k16.row.col.f32.f16.f16.f32 "
        "{%0,%1,%2,%3}, {%4,%5,%6,%7}, {%8,%9}, {%0,%1,%2,%3};"
        : "+f"(c[0]), "+f"(c[1]), "+f"(c[2]), "+f"(c[3])
        : "r"(a[0]), "r"(a[1]), "r"(a[2]), "r"(a[3]), "r"(b0), "r"(b1));
}

// PDL device controls (sm_90+): wait for upstream grid's data, signal downstream.
DINL void pdl_wait()    { cudaGridDependencySynchronize(); }
DINL void pdl_trigger() { cudaTriggerProgrammaticLaunchCompletion(); }

// ---------------- shared mainloop (CTA 128x128, 4 warps 2x2, warp 64x64) ----------------
template <typename F>
DINL void run_mainloop(const __half* __restrict__ A, const __half* __restrict__ B,
                       int lda, int ldb, int m0, int n0, int nT,
                       char* smraw, int tid, int wm, int wn, int lane, float (*acc)[8][4])
{
    __half* As = (__half*)smraw;
    __half* Bs = As + NSTG * TSTG;

    auto load = [&](int stage, int t) {
        __half* da = As + stage * TSTG;
        __half* db = Bs + stage * TSTG;
#pragma unroll
        for (int i = 0; i < 8; i++) {
            const int j = i * 128 + tid;
            const int r = j >> 3, c = (j & 7) << 3;
            cp_async16((uint32_t)__cvta_generic_to_shared(da + r * STR + c),
                       A + (long)(m0 + r) * lda + t * BK + c);
            cp_async16((uint32_t)__cvta_generic_to_shared(db + r * STR + c),
                       B + (long)(n0 + r) * ldb + t * BK + c);
        }
    };

    load(0, 0); cp_commit();
    load(1, 1); cp_commit();

    const uint32_t aB = (uint32_t)__cvta_generic_to_shared(As) +
        ((((wm * 64 + (lane & 15)) * STR) + ((lane >> 4) << 3)) << 1);
    const uint32_t bB = (uint32_t)__cvta_generic_to_shared(Bs) +
        ((((wn * 64 + (lane & 15)) * STR) + ((lane >> 4) << 3)) << 1);

    uint32_t a[2][4][4], b[2][4][4];
    int st = 0;
    for (int t = 0; t < nT; t++) {
        cp_wait1();
        __syncthreads();
        if (t + 2 < nT) load(st == 0 ? 2 : st - 1, t + 2);
        cp_commit();

        const uint32_t aS = aB + st * (TSTG * 2);
        const uint32_t bS = bB + st * (TSTG * 2);

#pragma unroll
        for (int mt = 0; mt < 4; mt++) ldsm4(a[0][mt], aS + mt * (16 * STR * 2));
#pragma unroll
        for (int gb = 0; gb < 4; gb++) ldsm4(b[0][gb], bS + gb * (16 * STR * 2));

#pragma unroll
        for (int ks = 0; ks < 4; ks++) {
            const int cur = ks & 1, nxt = cur ^ 1;
            if (ks < 3) {
#pragma unroll
                for (int mt = 0; mt < 4; mt++)
                    ldsm4(a[nxt][mt], aS + mt * (16 * STR * 2) + (ks + 1) * 32);
#pragma unroll
                for (int gb = 0; gb < 4; gb++)
                    ldsm4(b[nxt][gb], bS + gb * (16 * STR * 2) + (ks + 1) * 32);
            }
#pragma unroll
            for (int mt = 0; mt < 4; mt++)
#pragma unroll
                for (int nt = 0; nt < 8; nt++)
                    mma16816(acc[mt][nt], a[cur][mt],
                             b[cur][nt >> 1][nt & 1], b[cur][nt >> 1][(nt & 1) + 2]);
        }
        st = (st == 2) ? 0 : st + 1;
    }
    __syncthreads();
}
template <typename T> struct Tag {};

// =====================================================================
// Templated GEMM (used for QKproj and PV).
// =====================================================================
template <int BIASM, bool KLIM, bool OUTH, bool NORM>
__global__ __launch_bounds__(128, 2) void gemm_h(
    const __half* __restrict__ A, const __half* __restrict__ B,
    const float* __restrict__ bias, void* __restrict__ Cv,
    int lda, int ldb, int ldc, long sAb, long sBb, long sCb, int Ktot)
{
    pdl_wait();   // upstream grid's stores visible from here on

    const int bx = blockIdx.x, by = blockIdx.y, bz = blockIdx.z;
    const int nT = (KLIM ? (by + 1) * BM : Ktot) / BK;

    A += (long)bz * sAb;
    B += (long)bz * sBb;
    const int m0 = by * BM, n0 = bx * BN;

    extern __shared__ __align__(16) char smraw[];
    float* sext = (float*)(smraw + EXT_OFF);

    const int tid = threadIdx.x, warp = tid >> 5, lane = tid & 31;
    const int wm = warp >> 1, wn = warp & 1;

    if (NORM) {
        const int q = m0 + tid;
        const float* rp = g_rsp + ((long)bz * SEQ + q) * 16;
        float s = 0.f;
        const int pm = q >> 7;
        for (int p = 0; p <= pm; p++) s += rp[p];
        sext[tid] = 1.f / s;
        __syncthreads();
    }

    float acc[4][8][4];
#pragma unroll
    for (int i = 0; i < 4; i++)
#pragma unroll
        for (int j = 0; j < 8; j++)
#pragma unroll
            for (int k = 0; k < 4; k++) acc[i][j][k] = 0.f;

    run_mainloop<Tag<void>>(A, B, lda, ldb, m0, n0, nT, smraw, tid, wm, wn, lane, acc);

    const int g = lane >> 2, cth = lane & 3;
#pragma unroll
    for (int mt = 0; mt < 4; mt++) {
        const int lr = wm * 64 + mt * 16 + g;
        const int rr = m0 + lr;
        float rb0 = 0.f, rb1 = 0.f;
        if (BIASM == 2) { rb0 = __ldg(bias + rr); rb1 = __ldg(bias + rr + 8); }
        float inv0 = 1.f, inv1 = 1.f;
        if (NORM) { inv0 = sext[lr]; inv1 = sext[lr + 8]; }
#pragma unroll
        for (int nt = 0; nt < 8; nt++) {
            const int cc = n0 + wn * 64 + nt * 8 + (cth << 1);
            float b0 = 0.f, b1 = 0.f;
            if (BIASM == 1) { b0 = __ldg(bias + cc); b1 = __ldg(bias + cc + 1); }
            float v00 = acc[mt][nt][0] + (BIASM == 2 ? rb0 : b0);
            float v01 = acc[mt][nt][1] + (BIASM == 2 ? rb0 : b1);
            float v10 = acc[mt][nt][2] + (BIASM == 2 ? rb1 : b0);
            float v11 = acc[mt][nt][3] + (BIASM == 2 ? rb1 : b1);
            if (NORM) { v00 *= inv0; v01 *= inv0; v10 *= inv1; v11 *= inv1; }
            if (OUTH) {
                __half* C = (__half*)Cv + (long)bz * sCb;
                *(__half2*)(C + (long)rr * ldc + cc)       = __floats2half2_rn(v00, v01);
                *(__half2*)(C + (long)(rr + 8) * ldc + cc) = __floats2half2_rn(v10, v11);
            } else {
                float* C = (float*)Cv + (long)bz * sCb;
                *(float2*)(C + (long)rr * ldc + cc)       = make_float2(v00, v01);
                *(float2*)(C + (long)(rr + 8) * ldc + cc) = make_float2(v10, v11);
            }
        }
    }
    pdl_trigger();   // all this CTA's stores are issued; allow downstream launch
}

// =====================================================================
// Fused phase-2 kernel: QKT (exp+mask+rowsum) CTAs and Vproj CTAs in ONE
// launch, so SMs interleave their stalls. grid (136 + 64, 1, BATCH).
// =====================================================================
__global__ __launch_bounds__(128, 2) void k_p2(const float* __restrict__ bv)
{
    pdl_wait();

    const int bz = blockIdx.z;
    const bool qkt = blockIdx.x < 136;
    int bx, by, lda, ldb, ldc;
    const __half *A, *B;
    __half* C;

    if (qkt) {   // packed lower-triangular index -> (by, bx), bx <= by
        const int i = blockIdx.x;
        int r = (int)((sqrtf(8.f * i + 1.f) - 1.f) * 0.5f);
        while ((r + 1) * (r + 2) / 2 <= i) r++;
        while (r * (r + 1) / 2 > i) r--;
        by = r;
        bx = i - r * (r + 1) / 2;
        A = g_QKh + (long)bz * SEQ * 2 * DIM;          // Q rows
        B = g_QKh + (long)bz * SEQ * 2 * DIM + DIM;    // K rows
        lda = ldb = 2 * DIM;
        C = g_Ph + (long)bz * SEQ * SEQ;
        ldc = SEQ;
    } else {     // Vproj tile: V^T[b] = Wvt @ xh[b]^T + bv[row]
        const int j = blockIdx.x - 136;                 // 0..63
        bx = j & 15;                                    // seq tile (n)
        by = j >> 4;                                    // odim tile (m), 0..3
        A = g_Wvt;
        lda = DIM;
        B = g_xh + (long)bz * SEQ * DIM;
        ldb = DIM;
        C = g_Vth + (long)bz * ODIM * SEQ;
        ldc = SEQ;
    }
    const int m0 = by * BM, n0 = bx * BN;
    const int nT = DIM / BK;   // 16 for both modes

    extern __shared__ __align__(16) char smraw[];
    float* sext = (float*)(smraw + EXT_OFF);

    const int tid = threadIdx.x, warp = tid >> 5, lane = tid & 31;
    const int wm = warp >> 1, wn = warp & 1;

    float acc[4][8][4];
#pragma unroll
    for (int i = 0; i < 4; i++)
#pragma unroll
        for (int j = 0; j < 8; j++)
#pragma unroll
            for (int k = 0; k < 4; k++) acc[i][j][k] = 0.f;

    run_mainloop<Tag<void>>(A, B, lda, ldb, m0, n0, nT, smraw, tid, wm, wn, lane, acc);

    // ---- epilogue (runtime mode) ----
    const int g = lane >> 2, cth = lane & 3;
    float rsum[8];
#pragma unroll
    for (int i = 0; i < 8; i++) rsum[i] = 0.f;

#pragma unroll
    for (int mt = 0; mt < 4; mt++) {
        const int lr = wm * 64 + mt * 16 + g;
        const int rr = m0 + lr;
        float rb0 = 0.f, rb1 = 0.f;
        if (!qkt) { rb0 = __ldg(bv + rr); rb1 = __ldg(bv + rr + 8); }
#pragma unroll
        for (int nt = 0; nt < 8; nt++) {
            const int cc = n0 + wn * 64 + nt * 8 + (cth << 1);
            float v00 = acc[mt][nt][0] + rb0;
            float v01 = acc[mt][nt][1] + rb0;
            float v10 = acc[mt][nt][2] + rb1;
            float v11 = acc[mt][nt][3] + rb1;
            if (qkt) {   // causal mask + exp (max-free: |s*scale| ~ O(2))
                v00 = (cc     <= rr    ) ? __expf(v00 * SCALE) : 0.f;
                v01 = (cc + 1 <= rr    ) ? __expf(v01 * SCALE) : 0.f;
                v10 = (cc     <= rr + 8) ? __expf(v10 * SCALE) : 0.f;
                v11 = (cc + 1 <= rr + 8) ? __expf(v11 * SCALE) : 0.f;
                rsum[mt * 2]     += v00 + v01;
                rsum[mt * 2 + 1] += v10 + v11;
            }
            *(__half2*)(C + (long)rr * ldc + cc)       = __floats2half2_rn(v00, v01);
            *(__half2*)(C + (long)(rr + 8) * ldc + cc) = __floats2half2_rn(v10, v11);
        }
    }

    if (qkt) {   // deterministic rowsum partials: quad shfl -> smem -> global
#pragma unroll
        for (int i = 0; i < 8; i++) {
            rsum[i] += __shfl_xor_sync(0xffffffffu, rsum[i], 1);
            rsum[i] += __shfl_xor_sync(0xffffffffu, rsum[i], 2);
        }
        if (cth == 0) {
#pragma unroll
            for (int mt = 0; mt < 4; mt++) {
                sext[wn * BM + wm * 64 + mt * 16 + g]     = rsum[mt * 2];
                sext[wn * BM + wm * 64 + mt * 16 + g + 8] = rsum[mt * 2 + 1];
            }
        }
        __syncthreads();
        const float s = sext[tid] + sext[BM + tid];
        g_rsp[((long)bz * SEQ + m0 + tid) * 16 + bx] = s;
    }
    pdl_trigger();
}

// ---------------- prep kernels (2 launches total) ----------------
__global__ __launch_bounds__(256) void k_f2h(const float4* __restrict__ in,
                                             __half2* __restrict__ out, int n4)
{
    const int i = blockIdx.x * blockDim.x + threadIdx.x;
    if (i < n4) {
        const float4 v = in[i];
        out[2 * i]     = __floats2half2_rn(v.x, v.y);
        out[2 * i + 1] = __floats2half2_rn(v.z, v.w);
    }
}

// One launch: Wq^T, Wk^T -> Wqkt, Wv^T -> Wvt, bias pack.
__global__ __launch_bounds__(256) void k_prep_w(
    const float* __restrict__ Wq, const float* __restrict__ Wk,
    const float* __restrict__ Wv, const float* __restrict__ bq,
    const float* __restrict__ bk)
{
    const int z = blockIdx.z;
    if (z == 2 && blockIdx.x >= 16) {           // bias pack on spare blocks
        const int i = (blockIdx.x - 16) * 256 + (threadIdx.y * 32 + threadIdx.x);
        if (i < 2 * DIM) g_bqk[i] = (i < DIM) ? bq[i] : bk[i - DIM];
        return;
    }
    const float* W = (z == 0) ? Wq : (z == 1) ? Wk : Wv;
    __half* Wt     = (z == 2) ? g_Wvt : g_Wqkt;
    const int N    = (z == 2) ? ODIM : DIM;
    const int roff = (z == 1) ? DIM : 0;

    __shared__ float t[32][33];
    const int n0 = blockIdx.x * 32, k0 = blockIdx.y * 32;
    const int x = threadIdx.x, y = threadIdx.y;
#pragma unroll
    for (int r = 0; r < 32; r += 8) t[y + r][x] = W[(long)(k0 + y + r) * N + n0 + x];
    __syncthreads();
#pragma unroll
    for (int r = 0; r < 32; r += 8)
        Wt[(long)(roff + n0 + y + r) * DIM + k0 + x] = __float2half(t[x][y + r]);
}

// ---------------- host side ----------------
template <typename K, typename... Args>
static void launch_pdl(K kern, dim3 grid, dim3 block, int smem, Args... args)
{
    cudaLaunchConfig_t cfg = {};
    cfg.gridDim = grid;
    cfg.blockDim = block;
    cfg.dynamicSmemBytes = (size_t)smem;
    cfg.stream = 0;
    cudaLaunchAttribute at[1];
    at[0].id = cudaLaunchAttributeProgrammaticStreamSerialization;
    at[0].val.programmaticStreamSerializationAllowed = 1;
    cfg.attrs = at;
    cfg.numAttrs = 1;
    cudaLaunchKernelEx(&cfg, kern, args...);
}

extern "C" void kernel_launch(void* const* d_in, const int* in_sizes, int n_in,
                              void* d_out, int out_size)
{
    (void)in_sizes; (void)n_in; (void)out_size;
    const float* x  = (const float*)d_in[0];
    const float* Wq = (const float*)d_in[1];
    const float* bq = (const float*)d_in[2];
    const float* Wk = (const float*)d_in[3];
    const float* bk = (const float*)d_in[4];
    const float* Wv = (const float*)d_in[5];
    const float* bv = (const float*)d_in[6];
    float* out = (float*)d_out;

    __half *xh, *Wqkt, *QKh, *Vth, *Ph;
    float* bqk;
    cudaGetSymbolAddress((void**)&xh,   g_xh);
    cudaGetSymbolAddress((void**)&Wqkt, g_Wqkt);
    cudaGetSymbolAddress((void**)&bqk,  g_bqk);
    cudaGetSymbolAddress((void**)&QKh,  g_QKh);
    cudaGetSymbolAddress((void**)&Vth,  g_Vth);
    cudaGetSymbolAddress((void**)&Ph,   g_Ph);

    cudaFuncSetAttribute(gemm_h<1, false, true, false>,
                         cudaFuncAttributeMaxDynamicSharedMemorySize, SMEM_TOTAL);
    cudaFuncSetAttribute(k_p2,
                         cudaFuncAttributeMaxDynamicSharedMemorySize, SMEM_TOTAL);
    cudaFuncSetAttribute(gemm_h<0, true, false, true>,
                         cudaFuncAttributeMaxDynamicSharedMemorySize, SMEM_TOTAL);

    const int MTOT = BATCH * SEQ;   // 16384

    // ---- prep (2 launches, plain) ----
    k_f2h<<<(MTOT * DIM / 4 + 255) / 256, 256>>>((const float4*)x, (__half2*)xh, MTOT * DIM / 4);
    k_prep_w<<<dim3(32, 32, 3), dim3(32, 8)>>>(Wq, Wk, Wv, bq, bk);

    // ---- QK = xh @ [Wqt|Wkt]^T + bqk  [16384 x 2048], fp16 out (PDL) ----
    launch_pdl(gemm_h<1, false, true, false>,
               dim3(2 * DIM / BN, MTOT / BM, 1), dim3(128), SMEM_TOTAL,
               (const __half*)xh, (const __half*)Wqkt, (const float*)bqk, (void*)QKh,
               (int)DIM, (int)DIM, (int)(2 * DIM), (long)0, (long)0, (long)0, (int)DIM);

    // ---- fused phase 2: QKT (exp-scores + rowsums) AND Vproj, one launch (PDL) ----
    launch_pdl(k_p2, dim3(136 + 64, 1, BATCH), dim3(128), SMEM_TOTAL, (const float*)bv);

    // ---- out[b] = (Ph[b] @ Vth[b]^T) / rowsum  (K causally limited) (PDL) ----
    launch_pdl(gemm_h<0, true, false, true>,
               dim3(ODIM / BN, SEQ / BM, BATCH), dim3(128), SMEM_TOTAL,
               (const __half*)Ph, (const __half*)Vth, (const float*)nullptr, (void*)out,
               (int)SEQ, (int)SEQ, (int)ODIM,
               (long)SEQ * SEQ, (long)ODIM * SEQ, (long)SEQ * ODIM, (int)SEQ);
}

// round 14
// speedup vs baseline: 1.2526x; 1.1542x over previous
#include <cuda_runtime.h>
#include <cuda_fp16.h>
#include <cstdint>

#define DINL __device__ __forceinline__

static constexpr int BATCH = 8;
static constexpr int SEQ   = 2048;
static constexpr int DIM   = 1024;
static constexpr int ODIM  = 512;

// ---------------- scratch (device globals; allocation-free) ----------------
__device__ __align__(1024) __half g_xh [(size_t)BATCH * SEQ * DIM];   // 32 MB
__device__ __align__(1024) __half g_Wqh[(size_t)DIM * DIM];           //  2 MB Wq fp16 [a][e]
__device__ __align__(1024) __half g_Wkh[(size_t)DIM * DIM];           //  2 MB Wk fp16 [b][e]
__device__ __align__(1024) __half g_Wvt[(size_t)ODIM * DIM];          //  1 MB Wv^T [o][k]
__device__ __align__(1024) __half g_Gt [(size_t)DIM * DIM];           //  2 MB G^T = Wk Wq^T
__device__ __align__(1024) __half g_Th [(size_t)BATCH * SEQ * DIM];   // 32 MB T = x@G
__device__ __align__(1024) __half g_Vth[(size_t)BATCH * ODIM * SEQ];  // 16 MB V^T per batch
__device__ __align__(1024) __half g_Ph [(size_t)BATCH * SEQ * SEQ];   // 64 MB exp-scores
__device__ __align__(1024) float  g_rsp[(size_t)BATCH * SEQ * 16];    //  1 MB rowsum partials
__device__ __align__(16)   float  g_vq [DIM];                         // Wq @ bk
__device__ __align__(16)   float  g_vk [DIM];                         // Wk @ bq
__device__ __align__(16)   float  g_u  [(size_t)BATCH * SEQ];         // SCALE * x.vq
__device__ __align__(16)   float  g_w  [(size_t)BATCH * SEQ];         // SCALE * (x.vk + c)
__device__ float g_c;

// ------- GEMM config: CTA 128x128, 4 warps (2x2), warp 64x64, BK=64, 3 stages -------
static constexpr int BM = 128, BN = 128, BK = 64;
static constexpr int STR  = BK + 8;                 // 72 halves/row
static constexpr int TSTG = BM * STR;               // 9216 halves per tile stage
static constexpr int NSTG = 3;
static constexpr int EXT_OFF = NSTG * 2 * TSTG * 2; // 110592 B
static constexpr int SMEM_TOTAL = EXT_OFF + 2048;   // + f32 scratch (512 floats)

static constexpr float SCALE = 0.03125f;            // 1/sqrt(1024)

DINL void cp_async16(uint32_t smem_addr, const void* gmem) {
    asm volatile("cp.async.cg.shared.global [%0], [%1], 16;\n" :: "r"(smem_addr), "l"(gmem));
}
DINL void cp_commit() { asm volatile("cp.async.commit_group;\n"); }
DINL void cp_wait1()  { asm volatile("cp.async.wait_group 1;\n"); }

DINL void ldsm4(uint32_t* r, uint32_t addr) {
    asm volatile("ldmatrix.sync.aligned.m8n8.x4.shared.b16 {%0,%1,%2,%3}, [%4];"
                 : "=r"(r[0]), "=r"(r[1]), "=r"(r[2]), "=r"(r[3]) : "r"(addr));
}
DINL void mma16816(float* c, const uint32_t* a, uint32_t b0, uint32_t b1) {
    asm volatile(
        "mma.sync.aligned.m16n8k16.row.col.f32.f16.f16.f32 "
        "{%0,%1,%2,%3}, {%4,%5,%6,%7}, {%8,%9}, {%0,%1,%2,%3};"
        : "+f"(c[0]), "+f"(c[1]), "+f"(c[2]), "+f"(c[3])
        : "r"(a[0]), "r"(a[1]), "r"(a[2]), "r"(a[3]), "r"(b0), "r"(b1));
}

DINL void pdl_wait()    { cudaGridDependencySynchronize(); }
DINL void pdl_trigger() { cudaTriggerProgrammaticLaunchCompletion(); }

// ---------------- shared mainloop (CTA 128x128, 4 warps 2x2, warp 64x64) ----------------
DINL void run_mainloop(const __half* __restrict__ A, const __half* __restrict__ B,
                       int lda, int ldb, int m0, int n0, int nT,
                       char* smraw, int tid, int wm, int wn, int lane, float (*acc)[8][4])
{
    __half* As = (__half*)smraw;
    __half* Bs = As + NSTG * TSTG;

    auto load = [&](int stage, int t) {
        __half* da = As + stage * TSTG;
        __half* db = Bs + stage * TSTG;
#pragma unroll
        for (int i = 0; i < 8; i++) {
            const int j = i * 128 + tid;
            const int r = j >> 3, c = (j & 7) << 3;
            cp_async16((uint32_t)__cvta_generic_to_shared(da + r * STR + c),
                       A + (long)(m0 + r) * lda + t * BK + c);
            cp_async16((uint32_t)__cvta_generic_to_shared(db + r * STR + c),
                       B + (long)(n0 + r) * ldb + t * BK + c);
        }
    };

    load(0, 0); cp_commit();
    load(1, 1); cp_commit();

    const uint32_t aB = (uint32_t)__cvta_generic_to_shared(As) +
        ((((wm * 64 + (lane & 15)) * STR) + ((lane >> 4) << 3)) << 1);
    const uint32_t bB = (uint32_t)__cvta_generic_to_shared(Bs) +
        ((((wn * 64 + (lane & 15)) * STR) + ((lane >> 4) << 3)) << 1);

    uint32_t a[2][4][4], b[2][4][4];
    int st = 0;
    for (int t = 0; t < nT; t++) {
        cp_wait1();
        __syncthreads();
        if (t + 2 < nT) load(st == 0 ? 2 : st - 1, t + 2);
        cp_commit();

        const uint32_t aS = aB + st * (TSTG * 2);
        const uint32_t bS = bB + st * (TSTG * 2);

#pragma unroll
        for (int mt = 0; mt < 4; mt++) ldsm4(a[0][mt], aS + mt * (16 * STR * 2));
#pragma unroll
        for (int gb = 0; gb < 4; gb++) ldsm4(b[0][gb], bS + gb * (16 * STR * 2));

#pragma unroll
        for (int ks = 0; ks < 4; ks++) {
            const int cur = ks & 1, nxt = cur ^ 1;
            if (ks < 3) {
#pragma unroll
                for (int mt = 0; mt < 4; mt++)
                    ldsm4(a[nxt][mt], aS + mt * (16 * STR * 2) + (ks + 1) * 32);
#pragma unroll
                for (int gb = 0; gb < 4; gb++)
                    ldsm4(b[nxt][gb], bS + gb * (16 * STR * 2) + (ks + 1) * 32);
            }
#pragma unroll
            for (int mt = 0; mt < 4; mt++)
#pragma unroll
                for (int nt = 0; nt < 8; nt++)
                    mma16816(acc[mt][nt], a[cur][mt],
                             b[cur][nt >> 1][nt & 1], b[cur][nt >> 1][(nt & 1) + 2]);
        }
        st = (st == 2) ? 0 : st + 1;
    }
    __syncthreads();
}

// =====================================================================
// Generic GEMM (used for G^T and PV).
// =====================================================================
template <bool KLIM, bool OUTH, bool NORM>
__global__ __launch_bounds__(128, 2) void gemm_h(
    const __half* __restrict__ A, const __half* __restrict__ B,
    void* __restrict__ Cv,
    int lda, int ldb, int ldc, long sAb, long sBb, long sCb, int Ktot)
{
    pdl_wait();

    const int bx = blockIdx.x, by = blockIdx.y, bz = blockIdx.z;
    const int nT = (KLIM ? (by + 1) * BM : Ktot) / BK;

    A += (long)bz * sAb;
    B += (long)bz * sBb;
    const int m0 = by * BM, n0 = bx * BN;

    extern __shared__ __align__(16) char smraw[];
    float* sext = (float*)(smraw + EXT_OFF);

    const int tid = threadIdx.x, warp = tid >> 5, lane = tid & 31;
    const int wm = warp >> 1, wn = warp & 1;

    if (NORM) {
        const int q = m0 + tid;
        const float* rp = g_rsp + ((long)bz * SEQ + q) * 16;
        float s = 0.f;
        const int pm = q >> 7;
        for (int p = 0; p <= pm; p++) s += rp[p];
        sext[tid] = 1.f / s;
        __syncthreads();
    }

    float acc[4][8][4];
#pragma unroll
    for (int i = 0; i < 4; i++)
#pragma unroll
        for (int j = 0; j < 8; j++)
#pragma unroll
            for (int k = 0; k < 4; k++) acc[i][j][k] = 0.f;

    run_mainloop(A, B, lda, ldb, m0, n0, nT, smraw, tid, wm, wn, lane, acc);

    const int g = lane >> 2, cth = lane & 3;
#pragma unroll
    for (int mt = 0; mt < 4; mt++) {
        const int lr = wm * 64 + mt * 16 + g;
        const int rr = m0 + lr;
        float inv0 = 1.f, inv1 = 1.f;
        if (NORM) { inv0 = sext[lr]; inv1 = sext[lr + 8]; }
#pragma unroll
        for (int nt = 0; nt < 8; nt++) {
            const int cc = n0 + wn * 64 + nt * 8 + (cth << 1);
            float v00 = acc[mt][nt][0], v01 = acc[mt][nt][1];
            float v10 = acc[mt][nt][2], v11 = acc[mt][nt][3];
            if (NORM) { v00 *= inv0; v01 *= inv0; v10 *= inv1; v11 *= inv1; }
            if (OUTH) {
                __half* C = (__half*)Cv + (long)bz * sCb;
                *(__half2*)(C + (long)rr * ldc + cc)       = __floats2half2_rn(v00, v01);
                *(__half2*)(C + (long)(rr + 8) * ldc + cc) = __floats2half2_rn(v10, v11);
            } else {
                float* C = (float*)Cv + (long)bz * sCb;
                *(float2*)(C + (long)rr * ldc + cc)       = make_float2(v00, v01);
                *(float2*)(C + (long)(rr + 8) * ldc + cc) = make_float2(v10, v11);
            }
        }
    }
    pdl_trigger();
}

// =====================================================================
// Mixed phase: Tproj (T = x@G, 128 tiles/batch) + Vproj (64 tiles/batch).
// =====================================================================
__global__ __launch_bounds__(128, 2) void k_p1b(const float* __restrict__ bv)
{
    pdl_wait();

    const int bz = blockIdx.z;
    const bool tp = blockIdx.x < 128;
    int bx, by, lda, ldb, ldc;
    const __half *A, *B;
    __half* C;

    if (tp) {                                       // T[i][b] = sum_a x[i][a] Gt[b][a]
        by = blockIdx.x >> 3; bx = blockIdx.x & 7;  // 16 m-tiles x 8 n-tiles
        A = g_xh + (long)bz * SEQ * DIM; lda = DIM;
        B = g_Gt;                        ldb = DIM;
        C = g_Th + (long)bz * SEQ * DIM; ldc = DIM;
    } else {                                        // V^T[o][s] = Wvt[o].x[s] + bv[o]
        const int j = blockIdx.x - 128;
        bx = j & 15; by = j >> 4;
        A = g_Wvt;                        lda = DIM;
        B = g_xh + (long)bz * SEQ * DIM;  ldb = DIM;
        C = g_Vth + (long)bz * ODIM * SEQ; ldc = SEQ;
    }
    const int m0 = by * BM, n0 = bx * BN;

    extern __shared__ __align__(16) char smraw[];
    const int tid = threadIdx.x, warp = tid >> 5, lane = tid & 31;
    const int wm = warp >> 1, wn = warp & 1;

    float acc[4][8][4];
#pragma unroll
    for (int i = 0; i < 4; i++)
#pragma unroll
        for (int j = 0; j < 8; j++)
#pragma unroll
            for (int k = 0; k < 4; k++) acc[i][j][k] = 0.f;

    run_mainloop(A, B, lda, ldb, m0, n0, DIM / BK, smraw, tid, wm, wn, lane, acc);

    const int g = lane >> 2, cth = lane & 3;
#pragma unroll
    for (int mt = 0; mt < 4; mt++) {
        const int rr = m0 + wm * 64 + mt * 16 + g;
        float rb0 = 0.f, rb1 = 0.f;
        if (!tp) { rb0 = __ldg(bv + rr); rb1 = __ldg(bv + rr + 8); }
#pragma unroll
        for (int nt = 0; nt < 8; nt++) {
            const int cc = n0 + wn * 64 + nt * 8 + (cth << 1);
            *(__half2*)(C + (long)rr * ldc + cc) =
                __floats2half2_rn(acc[mt][nt][0] + rb0, acc[mt][nt][1] + rb0);
            *(__half2*)(C + (long)(rr + 8) * ldc + cc) =
                __floats2half2_rn(acc[mt][nt][2] + rb1, acc[mt][nt][3] + rb1);
        }
    }
    pdl_trigger();
}

// =====================================================================
// QKT: Ph = exp(SCALE*(T @ x^T) + u[i] + w[j]) with causal mask + rowsums.
// Packed triangular grid (136, 1, BATCH).
// =====================================================================
__global__ __launch_bounds__(128, 2) void k_qkt()
{
    pdl_wait();

    const int bz = blockIdx.z;
    const int i = blockIdx.x;
    int r = (int)((sqrtf(8.f * i + 1.f) - 1.f) * 0.5f);
    while ((r + 1) * (r + 2) / 2 <= i) r++;
    while (r * (r + 1) / 2 > i) r--;
    const int by = r, bx = i - r * (r + 1) / 2;

    const __half* A = g_Th + (long)bz * SEQ * DIM;
    const __half* B = g_xh + (long)bz * SEQ * DIM;
    __half* C = g_Ph + (long)bz * SEQ * SEQ;
    const int m0 = by * BM, n0 = bx * BN;

    extern __shared__ __align__(16) char smraw[];
    float* sext = (float*)(smraw + EXT_OFF);   // [0..255] reduce, [256..383] u, [384..511] w

    const int tid = threadIdx.x, warp = tid >> 5, lane = tid & 31;
    const int wm = warp >> 1, wn = warp & 1;

    // preload pre-scaled bias fixups (visible after first mainloop barrier)
    sext[256 + tid] = __ldg(g_u + (long)bz * SEQ + m0 + tid);
    sext[384 + tid] = __ldg(g_w + (long)bz * SEQ + n0 + tid);

    float acc[4][8][4];
#pragma unroll
    for (int ii = 0; ii < 4; ii++)
#pragma unroll
        for (int j = 0; j < 8; j++)
#pragma unroll
            for (int k = 0; k < 4; k++) acc[ii][j][k] = 0.f;

    run_mainloop(A, B, DIM, DIM, m0, n0, DIM / BK, smraw, tid, wm, wn, lane, acc);

    const int g = lane >> 2, cth = lane & 3;
    float rsum[8];
#pragma unroll
    for (int ii = 0; ii < 8; ii++) rsum[ii] = 0.f;

#pragma unroll
    for (int mt = 0; mt < 4; mt++) {
        const int lr = wm * 64 + mt * 16 + g;
        const int rr = m0 + lr;
        const float u0 = sext[256 + lr], u1 = sext[256 + lr + 8];
#pragma unroll
        for (int nt = 0; nt < 8; nt++) {
            const int lc = wn * 64 + nt * 8 + (cth << 1);
            const int cc = n0 + lc;
            const float w0 = sext[384 + lc], w1 = sext[384 + lc + 1];
            float v00 = (cc     <= rr    ) ? __expf(fmaf(acc[mt][nt][0], SCALE, u0 + w0)) : 0.f;
            float v01 = (cc + 1 <= rr    ) ? __expf(fmaf(acc[mt][nt][1], SCALE, u0 + w1)) : 0.f;
            float v10 = (cc     <= rr + 8) ? __expf(fmaf(acc[mt][nt][2], SCALE, u1 + w0)) : 0.f;
            float v11 = (cc + 1 <= rr + 8) ? __expf(fmaf(acc[mt][nt][3], SCALE, u1 + w1)) : 0.f;
            rsum[mt * 2]     += v00 + v01;
            rsum[mt * 2 + 1] += v10 + v11;
            *(__half2*)(C + (long)rr * SEQ + cc)       = __floats2half2_rn(v00, v01);
            *(__half2*)(C + (long)(rr + 8) * SEQ + cc) = __floats2half2_rn(v10, v11);
        }
    }

    // deterministic rowsum partials: quad shfl -> smem -> global
#pragma unroll
    for (int ii = 0; ii < 8; ii++) {
        rsum[ii] += __shfl_xor_sync(0xffffffffu, rsum[ii], 1);
        rsum[ii] += __shfl_xor_sync(0xffffffffu, rsum[ii], 2);
    }
    if (cth == 0) {
#pragma unroll
        for (int mt = 0; mt < 4; mt++) {
            sext[wn * BM + wm * 64 + mt * 16 + g]     = rsum[mt * 2];
            sext[wn * BM + wm * 64 + mt * 16 + g + 8] = rsum[mt * 2 + 1];
        }
    }
    __syncthreads();
    const float s = sext[tid] + sext[BM + tid];
    g_rsp[((long)bz * SEQ + m0 + tid) * 16 + bx] = s;
    pdl_trigger();
}

// =====================================================================
// Prep 1: Wq/Wk straight convert, Wv^T transpose, vq = Wq@bk, vk = Wk@bq, c.
// grid (32, 32, 4), 256 threads.
// =====================================================================
__global__ __launch_bounds__(256) void k_prep_w(
    const float* __restrict__ Wq, const float* __restrict__ Wk,
    const float* __restrict__ Wv, const float* __restrict__ bq,
    const float* __restrict__ bk)
{
    const int z = blockIdx.z;
    const int tid = threadIdx.x;
    const int bid = blockIdx.y * 32 + blockIdx.x;

    if (z == 0 || z == 1) {        // straight convert, 1024 elems per block
        const float* W = (z == 0) ? Wq : Wk;
        __half2* dst = (__half2*)((z == 0) ? g_Wqh : g_Wkh);
        const float4 v = ((const float4*)W)[bid * 256 + tid];
        dst[bid * 512 + tid * 2]     = __floats2half2_rn(v.x, v.y);
        dst[bid * 512 + tid * 2 + 1] = __floats2half2_rn(v.z, v.w);
        return;
    }
    if (z == 2) {                   // Wv transpose (x<16) / c (x==16,y==0)
        if (blockIdx.x < 16) {
            __shared__ float t[32][33];
            const int n0 = blockIdx.x * 32, k0 = blockIdx.y * 32;
            const int x = tid & 31, y = tid >> 5;   // 32 x 8
#pragma unroll
            for (int rr = 0; rr < 32; rr += 8)
                t[y + rr][x] = Wv[(long)(k0 + y + rr) * ODIM + n0 + x];
            __syncthreads();
#pragma unroll
            for (int rr = 0; rr < 32; rr += 8)
                g_Wvt[(long)(n0 + y + rr) * DIM + k0 + x] = __float2half(t[x][y + rr]);
        } else if (blockIdx.x == 16 && blockIdx.y == 0) {   // c = bq.bk
            float s = 0.f;
            for (int e = tid; e < DIM; e += 256) s += bq[e] * bk[e];
#pragma unroll
            for (int o = 16; o; o >>= 1) s += __shfl_xor_sync(0xffffffffu, s, o);
            __shared__ float red[8];
            if ((tid & 31) == 0) red[tid >> 5] = s;
            __syncthreads();
            if (tid == 0) {
                float c = 0.f;
                for (int ii = 0; ii < 8; ii++) c += red[ii];
                g_c = c;
            }
        }
        return;
    }
    // z == 3: vq rows (bid<128) / vk rows (128<=bid<256), one warp per row
    if (bid >= 256) return;
    const int w = tid >> 5, lane = tid & 31;
    const bool isq = bid < 128;
    const int row = (isq ? bid : bid - 128) * 8 + w;
    const float* R = (isq ? Wq : Wk) + (long)row * DIM;
    const float* bvv = isq ? bk : bq;
    float s = 0.f;
    for (int e = lane; e < DIM; e += 32) s += R[e] * bvv[e];
#pragma unroll
    for (int o = 16; o; o >>= 1) s += __shfl_xor_sync(0xffffffffu, s, o);
    if (lane == 0) { if (isq) g_vq[row] = s; else g_vk[row] = s; }
}

// =====================================================================
// Prep 2: x -> fp16, and u/w row dots (one block per row of x).
// =====================================================================
__global__ __launch_bounds__(256) void k_f2h_uw(const float4* __restrict__ x4)
{
    const long row = blockIdx.x;
    const int tid = threadIdx.x;
    const float4 v = x4[row * 256 + tid];
    __half2* dst = (__half2*)g_xh + row * 512 + tid * 2;
    dst[0] = __floats2half2_rn(v.x, v.y);
    dst[1] = __floats2half2_rn(v.z, v.w);

    const float4 q4 = *(const float4*)(g_vq + tid * 4);
    const float4 k4 = *(const float4*)(g_vk + tid * 4);
    float du = v.x * q4.x + v.y * q4.y + v.z * q4.z + v.w * q4.w;
    float dw = v.x * k4.x + v.y * k4.y + v.z * k4.z + v.w * k4.w;
#pragma unroll
    for (int o = 16; o; o >>= 1) {
        du += __shfl_xor_sync(0xffffffffu, du, o);
        dw += __shfl_xor_sync(0xffffffffu, dw, o);
    }
    __shared__ float ru[8], rw[8];
    if ((tid & 31) == 0) { ru[tid >> 5] = du; rw[tid >> 5] = dw; }
    __syncthreads();
    if (tid == 0) {
        float su = 0.f, sw = 0.f;
#pragma unroll
        for (int ii = 0; ii < 8; ii++) { su += ru[ii]; sw += rw[ii]; }
        g_u[row] = SCALE * su;
        g_w[row] = SCALE * (sw + g_c);
    }
}

// ---------------- host side ----------------
template <typename K, typename... Args>
static void launch_pdl(K kern, dim3 grid, dim3 block, int smem, Args... args)
{
    cudaLaunchConfig_t cfg = {};
    cfg.gridDim = grid;
    cfg.blockDim = block;
    cfg.dynamicSmemBytes = (size_t)smem;
    cfg.stream = 0;
    cudaLaunchAttribute at[1];
    at[0].id = cudaLaunchAttributeProgrammaticStreamSerialization;
    at[0].val.programmaticStreamSerializationAllowed = 1;
    cfg.attrs = at;
    cfg.numAttrs = 1;
    cudaLaunchKernelEx(&cfg, kern, args...);
}

extern "C" void kernel_launch(void* const* d_in, const int* in_sizes, int n_in,
                              void* d_out, int out_size)
{
    (void)in_sizes; (void)n_in; (void)out_size;
    const float* x  = (const float*)d_in[0];
    const float* Wq = (const float*)d_in[1];
    const float* Wk = (const float*)d_in[3];
    const float* Wv = (const float*)d_in[5];
    const float* bq = (const float*)d_in[2];
    const float* bk = (const float*)d_in[4];
    const float* bv = (const float*)d_in[6];
    float* out = (float*)d_out;

    __half *Wqh, *Wkh, *Gt, *Ph, *Vth;
    cudaGetSymbolAddress((void**)&Wqh, g_Wqh);
    cudaGetSymbolAddress((void**)&Wkh, g_Wkh);
    cudaGetSymbolAddress((void**)&Gt,  g_Gt);
    cudaGetSymbolAddress((void**)&Ph,  g_Ph);
    cudaGetSymbolAddress((void**)&Vth, g_Vth);

    cudaFuncSetAttribute(gemm_h<false, true, false>,
                         cudaFuncAttributeMaxDynamicSharedMemorySize, SMEM_TOTAL);
    cudaFuncSetAttribute(gemm_h<true, false, true>,
                         cudaFuncAttributeMaxDynamicSharedMemorySize, SMEM_TOTAL);
    cudaFuncSetAttribute(k_p1b,
                         cudaFuncAttributeMaxDynamicSharedMemorySize, SMEM_TOTAL);
    cudaFuncSetAttribute(k_qkt,
                         cudaFuncAttributeMaxDynamicSharedMemorySize, SMEM_TOTAL);

    const int MTOT = BATCH * SEQ;   // 16384

    // ---- prep ----
    k_prep_w<<<dim3(32, 32, 4), 256>>>(Wq, Wk, Wv, bq, bk);
    k_f2h_uw<<<MTOT, 256>>>((const float4*)x);

    // ---- Gt = Wk @ Wq^T (K-major over e), fp16 [b][a] ----
    launch_pdl(gemm_h<false, true, false>, dim3(8, 8, 1), dim3(128), SMEM_TOTAL,
               (const __half*)Wkh, (const __half*)Wqh, (void*)Gt,
               (int)DIM, (int)DIM, (int)DIM, (long)0, (long)0, (long)0, (int)DIM);

    // ---- mixed: T = x@G and V^T = Wvt@x^T + bv, one launch ----
    launch_pdl(k_p1b, dim3(128 + 64, 1, BATCH), dim3(128), SMEM_TOTAL, (const float*)bv);

    // ---- Ph = exp(SCALE*T@x^T + u + w), causal + rowsum partials ----
    launch_pdl(k_qkt, dim3(136, 1, BATCH), dim3(128), SMEM_TOTAL);

    // ---- out = (Ph @ Vth^T) / rowsum  (K causally limited) ----
    launch_pdl(gemm_h<true, false, true>, dim3(ODIM / BN, SEQ / BM, BATCH), dim3(128), SMEM_TOTAL,
               (const __half*)Ph, (const __half*)Vth, (void*)out,
               (int)SEQ, (int)SEQ, (int)ODIM,
               (long)SEQ * SEQ, (long)ODIM * SEQ, (long)SEQ * ODIM, (int)SEQ);
}

// round 15
// speedup vs baseline: 1.3594x; 1.0852x over previous
#include <cuda_runtime.h>
#include <cuda_fp16.h>
#include <cstdint>

#define DINL __device__ __forceinline__

static constexpr int BATCH = 8;
static constexpr int SEQ   = 2048;
static constexpr int DIM   = 1024;
static constexpr int ODIM  = 512;

// ---------------- scratch (device globals; allocation-free) ----------------
__device__ __align__(1024) __half g_xh [(size_t)BATCH * SEQ * DIM];   // 32 MB
__device__ __align__(1024) __half g_Wqh[(size_t)DIM * DIM];           //  2 MB Wq fp16
__device__ __align__(1024) __half g_Wkh[(size_t)DIM * DIM];           //  2 MB Wk fp16
__device__ __align__(1024) __half g_Wvt[(size_t)ODIM * DIM];          //  1 MB Wv^T [o][k]
__device__ __align__(1024) __half g_Gt [(size_t)DIM * DIM];           //  2 MB G^T = Wk Wq^T
__device__ __align__(1024) __half g_Th [(size_t)BATCH * SEQ * DIM];   // 32 MB T = x@G
__device__ __align__(1024) __half g_Vth[(size_t)BATCH * ODIM * SEQ];  // 16 MB V^T per batch
__device__ __align__(1024) __half g_Ph [(size_t)BATCH * SEQ * SEQ];   // 64 MB exp-scores
__device__ __align__(1024) float  g_rsp[(size_t)BATCH * SEQ * 16];    //  1 MB rowsum partials
__device__ __align__(16)   float  g_vq [DIM];                         // Wq @ bk
__device__ __align__(16)   float  g_vk [DIM];                         // Wk @ bq
__device__ __align__(16)   float  g_u  [(size_t)BATCH * SEQ];         // SCALE * x.vq
__device__ __align__(16)   float  g_w  [(size_t)BATCH * SEQ];         // SCALE * (x.vk + c)
__device__ float    g_c;
__device__ unsigned g_ticket;                                         // job dispenser
__device__ unsigned g_rdy[BATCH * 16];                                // per-(b,row) done count

// ------- GEMM config: CTA 128x128, 4 warps (2x2), warp 64x64, BK=64, 3 stages -------
static constexpr int BM = 128, BN = 128, BK = 64;
static constexpr int STR  = BK + 8;                 // 72 halves/row
static constexpr int TSTG = BM * STR;               // 9216 halves per tile stage
static constexpr int NSTG = 3;
static constexpr int EXT_OFF = NSTG * 2 * TSTG * 2; // 110592 B
static constexpr int SMEM_TOTAL = EXT_OFF + 2048;   // + f32 scratch (512 floats)

static constexpr float SCALE = 0.03125f;            // 1/sqrt(1024)
static constexpr int N_QKT = 136 * BATCH;           // 1088 qkt jobs
static constexpr int N_PV  = 64 * BATCH;            // 512 pv jobs

DINL void cp_async16(uint32_t smem_addr, const void* gmem) {
    asm volatile("cp.async.cg.shared.global [%0], [%1], 16;\n" :: "r"(smem_addr), "l"(gmem));
}
DINL void cp_commit() { asm volatile("cp.async.commit_group;\n"); }
DINL void cp_wait1()  { asm volatile("cp.async.wait_group 1;\n"); }

DINL void ldsm4(uint32_t* r, uint32_t addr) {
    asm volatile("ldmatrix.sync.aligned.m8n8.x4.shared.b16 {%0,%1,%2,%3}, [%4];"
                 : "=r"(r[0]), "=r"(r[1]), "=r"(r[2]), "=r"(r[3]) : "r"(addr));
}
DINL void mma16816(float* c, const uint32_t* a, uint32_t b0, uint32_t b1) {
    asm volatile(
        "mma.sync.aligned.m16n8k16.row.col.f32.f16.f16.f32 "
        "{%0,%1,%2,%3}, {%4,%5,%6,%7}, {%8,%9}, {%0,%1,%2,%3};"
        : "+f"(c[0]), "+f"(c[1]), "+f"(c[2]), "+f"(c[3])
        : "r"(a[0]), "r"(a[1]), "r"(a[2]), "r"(a[3]), "r"(b0), "r"(b1));
}

DINL void pdl_wait()    { cudaGridDependencySynchronize(); }
DINL void pdl_trigger() { cudaTriggerProgrammaticLaunchCompletion(); }

// ---------------- shared mainloop (CTA 128x128, 4 warps 2x2, warp 64x64) ----------------
DINL void run_mainloop(const __half* __restrict__ A, const __half* __restrict__ B,
                       int lda, int ldb, int m0, int n0, int nT,
                       char* smraw, int tid, int wm, int wn, int lane, float (*acc)[8][4])
{
    __half* As = (__half*)smraw;
    __half* Bs = As + NSTG * TSTG;

    auto load = [&](int stage, int t) {
        __half* da = As + stage * TSTG;
        __half* db = Bs + stage * TSTG;
#pragma unroll
        for (int i = 0; i < 8; i++) {
            const int j = i * 128 + tid;
            const int r = j >> 3, c = (j & 7) << 3;
            cp_async16((uint32_t)__cvta_generic_to_shared(da + r * STR + c),
                       A + (long)(m0 + r) * lda + t * BK + c);
            cp_async16((uint32_t)__cvta_generic_to_shared(db + r * STR + c),
                       B + (long)(n0 + r) * ldb + t * BK + c);
        }
    };

    load(0, 0); cp_commit();
    load(1, 1); cp_commit();

    const uint32_t aB = (uint32_t)__cvta_generic_to_shared(As) +
        ((((wm * 64 + (lane & 15)) * STR) + ((lane >> 4) << 3)) << 1);
    const uint32_t bB = (uint32_t)__cvta_generic_to_shared(Bs) +
        ((((wn * 64 + (lane & 15)) * STR) + ((lane >> 4) << 3)) << 1);

    uint32_t a[2][4][4], b[2][4][4];
    int st = 0;
    for (int t = 0; t < nT; t++) {
        cp_wait1();
        __syncthreads();
        if (t + 2 < nT) load(st == 0 ? 2 : st - 1, t + 2);
        cp_commit();

        const uint32_t aS = aB + st * (TSTG * 2);
        const uint32_t bS = bB + st * (TSTG * 2);

#pragma unroll
        for (int mt = 0; mt < 4; mt++) ldsm4(a[0][mt], aS + mt * (16 * STR * 2));
#pragma unroll
        for (int gb = 0; gb < 4; gb++) ldsm4(b[0][gb], bS + gb * (16 * STR * 2));

#pragma unroll
        for (int ks = 0; ks < 4; ks++) {
            const int cur = ks & 1, nxt = cur ^ 1;
            if (ks < 3) {
#pragma unroll
                for (int mt = 0; mt < 4; mt++)
                    ldsm4(a[nxt][mt], aS + mt * (16 * STR * 2) + (ks + 1) * 32);
#pragma unroll
                for (int gb = 0; gb < 4; gb++)
                    ldsm4(b[nxt][gb], bS + gb * (16 * STR * 2) + (ks + 1) * 32);
            }
#pragma unroll
            for (int mt = 0; mt < 4; mt++)
#pragma unroll
                for (int nt = 0; nt < 8; nt++)
                    mma16816(acc[mt][nt], a[cur][mt],
                             b[cur][nt >> 1][nt & 1], b[cur][nt >> 1][(nt & 1) + 2]);
        }
        st = (st == 2) ? 0 : st + 1;
    }
    __syncthreads();
}

// =====================================================================
// Generic GEMM (used for G^T only).
// =====================================================================
__global__ __launch_bounds__(128, 2) void gemm_gt(
    const __half* __restrict__ A, const __half* __restrict__ B, __half* __restrict__ C)
{
    pdl_wait();
    const int m0 = blockIdx.y * BM, n0 = blockIdx.x * BN;
    extern __shared__ __align__(16) char smraw[];
    const int tid = threadIdx.x, warp = tid >> 5, lane = tid & 31;
    const int wm = warp >> 1, wn = warp & 1;

    float acc[4][8][4];
#pragma unroll
    for (int i = 0; i < 4; i++)
#pragma unroll
        for (int j = 0; j < 8; j++)
#pragma unroll
            for (int k = 0; k < 4; k++) acc[i][j][k] = 0.f;

    run_mainloop(A, B, DIM, DIM, m0, n0, DIM / BK, smraw, tid, wm, wn, lane, acc);

    const int g = lane >> 2, cth = lane & 3;
#pragma unroll
    for (int mt = 0; mt < 4; mt++) {
        const int rr = m0 + wm * 64 + mt * 16 + g;
#pragma unroll
        for (int nt = 0; nt < 8; nt++) {
            const int cc = n0 + wn * 64 + nt * 8 + (cth << 1);
            *(__half2*)(C + (long)rr * DIM + cc) =
                __floats2half2_rn(acc[mt][nt][0], acc[mt][nt][1]);
            *(__half2*)(C + (long)(rr + 8) * DIM + cc) =
                __floats2half2_rn(acc[mt][nt][2], acc[mt][nt][3]);
        }
    }
    pdl_trigger();
}

// =====================================================================
// Mixed phase: Tproj (T = x@G, 128 tiles/batch) + Vproj (64 tiles/batch).
// =====================================================================
__global__ __launch_bounds__(128, 2) void k_p1b(const float* __restrict__ bv)
{
    pdl_wait();

    const int bz = blockIdx.z;
    const bool tp = blockIdx.x < 128;
    int bx, by, lda, ldb, ldc;
    const __half *A, *B;
    __half* C;

    if (tp) {
        by = blockIdx.x >> 3; bx = blockIdx.x & 7;
        A = g_xh + (long)bz * SEQ * DIM; lda = DIM;
        B = g_Gt;                        ldb = DIM;
        C = g_Th + (long)bz * SEQ * DIM; ldc = DIM;
    } else {
        const int j = blockIdx.x - 128;
        bx = j & 15; by = j >> 4;
        A = g_Wvt;                         lda = DIM;
        B = g_xh + (long)bz * SEQ * DIM;   ldb = DIM;
        C = g_Vth + (long)bz * ODIM * SEQ; ldc = SEQ;
    }
    const int m0 = by * BM, n0 = bx * BN;

    extern __shared__ __align__(16) char smraw[];
    const int tid = threadIdx.x, warp = tid >> 5, lane = tid & 31;
    const int wm = warp >> 1, wn = warp & 1;

    float acc[4][8][4];
#pragma unroll
    for (int i = 0; i < 4; i++)
#pragma unroll
        for (int j = 0; j < 8; j++)
#pragma unroll
            for (int k = 0; k < 4; k++) acc[i][j][k] = 0.f;

    run_mainloop(A, B, lda, ldb, m0, n0, DIM / BK, smraw, tid, wm, wn, lane, acc);

    const int g = lane >> 2, cth = lane & 3;
#pragma unroll
    for (int mt = 0; mt < 4; mt++) {
        const int rr = m0 + wm * 64 + mt * 16 + g;
        float rb0 = 0.f, rb1 = 0.f;
        if (!tp) { rb0 = __ldg(bv + rr); rb1 = __ldg(bv + rr + 8); }
#pragma unroll
        for (int nt = 0; nt < 8; nt++) {
            const int cc = n0 + wn * 64 + nt * 8 + (cth << 1);
            *(__half2*)(C + (long)rr * ldc + cc) =
                __floats2half2_rn(acc[mt][nt][0] + rb0, acc[mt][nt][1] + rb0);
            *(__half2*)(C + (long)(rr + 8) * ldc + cc) =
                __floats2half2_rn(acc[mt][nt][2] + rb1, acc[mt][nt][3] + rb1);
        }
    }
    pdl_trigger();
}

// =====================================================================
// Fused attention phase: QKT jobs (tickets 0..1087, row-15-first) and PV
// jobs (tickets 1088..1599, heavy-first). PV spins on per-(b,row) counters.
// =====================================================================
__global__ __launch_bounds__(128, 2) void k_attn(float* __restrict__ out)
{
    pdl_wait();

    __shared__ unsigned sjob;
    const int tid = threadIdx.x, warp = tid >> 5, lane = tid & 31;
    const int wm = warp >> 1, wn = warp & 1;
    if (tid == 0) sjob = atomicAdd(&g_ticket, 1u);
    __syncthreads();
    const unsigned job = sjob;

    extern __shared__ __align__(16) char smraw[];
    float* sext = (float*)(smraw + EXT_OFF);   // [0..255] reduce, [256..383] u, [384..511] w

    float acc[4][8][4];
#pragma unroll
    for (int i = 0; i < 4; i++)
#pragma unroll
        for (int j = 0; j < 8; j++)
#pragma unroll
            for (int k = 0; k < 4; k++) acc[i][j][k] = 0.f;

    const int g = lane >> 2, cth = lane & 3;

    if (job < (unsigned)N_QKT) {
        // ---------------- QKT job ----------------
        const int bz = job & 7;
        const int i  = 135 - (int)(job >> 3);     // descending row order
        int r = (int)((sqrtf(8.f * i + 1.f) - 1.f) * 0.5f);
        while ((r + 1) * (r + 2) / 2 <= i) r++;
        while (r * (r + 1) / 2 > i) r--;
        const int by = r, bx = i - r * (r + 1) / 2;
        const int m0 = by * BM, n0 = bx * BN;

        const __half* A = g_Th + (long)bz * SEQ * DIM;
        const __half* B = g_xh + (long)bz * SEQ * DIM;
        __half* C = g_Ph + (long)bz * SEQ * SEQ;

        sext[256 + tid] = __ldg(g_u + (long)bz * SEQ + m0 + tid);
        sext[384 + tid] = __ldg(g_w + (long)bz * SEQ + n0 + tid);

        run_mainloop(A, B, DIM, DIM, m0, n0, DIM / BK, smraw, tid, wm, wn, lane, acc);

        float rsum[8];
#pragma unroll
        for (int ii = 0; ii < 8; ii++) rsum[ii] = 0.f;

#pragma unroll
        for (int mt = 0; mt < 4; mt++) {
            const int lr = wm * 64 + mt * 16 + g;
            const int rr = m0 + lr;
            const float u0 = sext[256 + lr], u1 = sext[256 + lr + 8];
#pragma unroll
            for (int nt = 0; nt < 8; nt++) {
                const int lc = wn * 64 + nt * 8 + (cth << 1);
                const int cc = n0 + lc;
                const float w0 = sext[384 + lc], w1 = sext[384 + lc + 1];
                float v00 = (cc     <= rr    ) ? __expf(fmaf(acc[mt][nt][0], SCALE, u0 + w0)) : 0.f;
                float v01 = (cc + 1 <= rr    ) ? __expf(fmaf(acc[mt][nt][1], SCALE, u0 + w1)) : 0.f;
                float v10 = (cc     <= rr + 8) ? __expf(fmaf(acc[mt][nt][2], SCALE, u1 + w0)) : 0.f;
                float v11 = (cc + 1 <= rr + 8) ? __expf(fmaf(acc[mt][nt][3], SCALE, u1 + w1)) : 0.f;
                rsum[mt * 2]     += v00 + v01;
                rsum[mt * 2 + 1] += v10 + v11;
                *(__half2*)(C + (long)rr * SEQ + cc)       = __floats2half2_rn(v00, v01);
                *(__half2*)(C + (long)(rr + 8) * SEQ + cc) = __floats2half2_rn(v10, v11);
            }
        }

#pragma unroll
        for (int ii = 0; ii < 8; ii++) {
            rsum[ii] += __shfl_xor_sync(0xffffffffu, rsum[ii], 1);
            rsum[ii] += __shfl_xor_sync(0xffffffffu, rsum[ii], 2);
        }
        if (cth == 0) {
#pragma unroll
            for (int mt = 0; mt < 4; mt++) {
                sext[wn * BM + wm * 64 + mt * 16 + g]     = rsum[mt * 2];
                sext[wn * BM + wm * 64 + mt * 16 + g + 8] = rsum[mt * 2 + 1];
            }
        }
        __syncthreads();
        g_rsp[((long)bz * SEQ + m0 + tid) * 16 + bx] = sext[tid] + sext[BM + tid];

        // release: make Ph + rsp visible, then bump the row counter
        __threadfence();
        __syncthreads();
        if (tid == 0) atomicAdd(&g_rdy[bz * 16 + by], 1u);
    } else {
        // ---------------- PV job ----------------
        const unsigned t2 = job - N_QKT;
        const int bz = t2 & 7;
        const int j  = (int)(t2 >> 3);            // 0..63
        const int by = 15 - (j >> 2);             // heavy rows first
        const int ox = j & 3;
        const int m0 = by * BM, n0 = ox * BN;
        const int nT = (by + 1) * 2;              // (by+1)*128 / BK

        // wait for all QKT tiles of this row
        if (tid == 0) {
            while (atomicAdd(&g_rdy[bz * 16 + by], 0u) < (unsigned)(by + 1)) __nanosleep(128);
        }
        __syncthreads();

        const float* rp = g_rsp + ((long)bz * SEQ + m0 + tid) * 16;
        float s = 0.f;
        for (int p = 0; p <= by; p++) s += __ldcg(rp + p);
        sext[tid] = 1.f / s;
        __syncthreads();

        const __half* A = g_Ph + (long)bz * SEQ * SEQ;
        const __half* B = g_Vth + (long)bz * ODIM * SEQ;
        float* C = out + (long)bz * SEQ * ODIM;

        run_mainloop(A, B, SEQ, SEQ, m0, n0, nT, smraw, tid, wm, wn, lane, acc);

#pragma unroll
        for (int mt = 0; mt < 4; mt++) {
            const int lr = wm * 64 + mt * 16 + g;
            const int rr = m0 + lr;
            const float inv0 = sext[lr], inv1 = sext[lr + 8];
#pragma unroll
            for (int nt = 0; nt < 8; nt++) {
                const int cc = n0 + wn * 64 + nt * 8 + (cth << 1);
                *(float2*)(C + (long)rr * ODIM + cc) =
                    make_float2(acc[mt][nt][0] * inv0, acc[mt][nt][1] * inv0);
                *(float2*)(C + (long)(rr + 8) * ODIM + cc) =
                    make_float2(acc[mt][nt][2] * inv1, acc[mt][nt][3] * inv1);
            }
        }
    }
}

// =====================================================================
// Prep 1: Wq/Wk convert, Wv^T transpose, vq/vk/c, and ticket/counter reset.
// =====================================================================
__global__ __launch_bounds__(256) void k_prep_w(
    const float* __restrict__ Wq, const float* __restrict__ Wk,
    const float* __restrict__ Wv, const float* __restrict__ bq,
    const float* __restrict__ bk)
{
    const int z = blockIdx.z;
    const int tid = threadIdx.x;
    const int bid = blockIdx.y * 32 + blockIdx.x;

    if (z == 0 || z == 1) {        // straight convert
        const float* W = (z == 0) ? Wq : Wk;
        __half2* dst = (__half2*)((z == 0) ? g_Wqh : g_Wkh);
        const float4 v = ((const float4*)W)[bid * 256 + tid];
        dst[bid * 512 + tid * 2]     = __floats2half2_rn(v.x, v.y);
        dst[bid * 512 + tid * 2 + 1] = __floats2half2_rn(v.z, v.w);
        return;
    }
    if (z == 2) {
        if (blockIdx.x < 16) {      // Wv transpose
            __shared__ float t[32][33];
            const int n0 = blockIdx.x * 32, k0 = blockIdx.y * 32;
            const int x = tid & 31, y = tid >> 5;
#pragma unroll
            for (int rr = 0; rr < 32; rr += 8)
                t[y + rr][x] = Wv[(long)(k0 + y + rr) * ODIM + n0 + x];
            __syncthreads();
#pragma unroll
            for (int rr = 0; rr < 32; rr += 8)
                g_Wvt[(long)(n0 + y + rr) * DIM + k0 + x] = __float2half(t[x][y + rr]);
        } else if (blockIdx.x == 16 && blockIdx.y == 0) {   // c = bq.bk
            float s = 0.f;
            for (int e = tid; e < DIM; e += 256) s += bq[e] * bk[e];
#pragma unroll
            for (int o = 16; o; o >>= 1) s += __shfl_xor_sync(0xffffffffu, s, o);
            __shared__ float red[8];
            if ((tid & 31) == 0) red[tid >> 5] = s;
            __syncthreads();
            if (tid == 0) {
                float c = 0.f;
                for (int ii = 0; ii < 8; ii++) c += red[ii];
                g_c = c;
            }
        } else if (blockIdx.x == 17 && blockIdx.y == 0) {   // reset dispatch state
            if (tid == 0) g_ticket = 0;
            if (tid < BATCH * 16) g_rdy[tid] = 0;
        }
        return;
    }
    // z == 3: vq rows (bid<128) / vk rows (128<=bid<256), one warp per row
    if (bid >= 256) return;
    const int w = tid >> 5, lane = tid & 31;
    const bool isq = bid < 128;
    const int row = (isq ? bid : bid - 128) * 8 + w;
    const float* R = (isq ? Wq : Wk) + (long)row * DIM;
    const float* bvv = isq ? bk : bq;
    float s = 0.f;
    for (int e = lane; e < DIM; e += 32) s += R[e] * bvv[e];
#pragma unroll
    for (int o = 16; o; o >>= 1) s += __shfl_xor_sync(0xffffffffu, s, o);
    if (lane == 0) { if (isq) g_vq[row] = s; else g_vk[row] = s; }
}

// =====================================================================
// Prep 2: x -> fp16, and u/w row dots (one block per row of x).
// =====================================================================
__global__ __launch_bounds__(256) void k_f2h_uw(const float4* __restrict__ x4)
{
    const long row = blockIdx.x;
    const int tid = threadIdx.x;
    const float4 v = x4[row * 256 + tid];
    __half2* dst = (__half2*)g_xh + row * 512 + tid * 2;
    dst[0] = __floats2half2_rn(v.x, v.y);
    dst[1] = __floats2half2_rn(v.z, v.w);

    const float4 q4 = *(const float4*)(g_vq + tid * 4);
    const float4 k4 = *(const float4*)(g_vk + tid * 4);
    float du = v.x * q4.x + v.y * q4.y + v.z * q4.z + v.w * q4.w;
    float dw = v.x * k4.x + v.y * k4.y + v.z * k4.z + v.w * k4.w;
#pragma unroll
    for (int o = 16; o; o >>= 1) {
        du += __shfl_xor_sync(0xffffffffu, du, o);
        dw += __shfl_xor_sync(0xffffffffu, dw, o);
    }
    __shared__ float ru[8], rw[8];
    if ((tid & 31) == 0) { ru[tid >> 5] = du; rw[tid >> 5] = dw; }
    __syncthreads();
    if (tid == 0) {
        float su = 0.f, sw = 0.f;
#pragma unroll
        for (int ii = 0; ii < 8; ii++) { su += ru[ii]; sw += rw[ii]; }
        g_u[row] = SCALE * su;
        g_w[row] = SCALE * (sw + g_c);
    }
}

// ---------------- host side ----------------
template <typename K, typename... Args>
static void launch_pdl(K kern, dim3 grid, dim3 block, int smem, Args... args)
{
    cudaLaunchConfig_t cfg = {};
    cfg.gridDim = grid;
    cfg.blockDim = block;
    cfg.dynamicSmemBytes = (size_t)smem;
    cfg.stream = 0;
    cudaLaunchAttribute at[1];
    at[0].id = cudaLaunchAttributeProgrammaticStreamSerialization;
    at[0].val.programmaticStreamSerializationAllowed = 1;
    cfg.attrs = at;
    cfg.numAttrs = 1;
    cudaLaunchKernelEx(&cfg, kern, args...);
}

extern "C" void kernel_launch(void* const* d_in, const int* in_sizes, int n_in,
                              void* d_out, int out_size)
{
    (void)in_sizes; (void)n_in; (void)out_size;
    const float* x  = (const float*)d_in[0];
    const float* Wq = (const float*)d_in[1];
    const float* bq = (const float*)d_in[2];
    const float* Wk = (const float*)d_in[3];
    const float* bk = (const float*)d_in[4];
    const float* Wv = (const float*)d_in[5];
    const float* bv = (const float*)d_in[6];
    float* out = (float*)d_out;

    __half *Wqh, *Wkh, *Gt;
    cudaGetSymbolAddress((void**)&Wqh, g_Wqh);
    cudaGetSymbolAddress((void**)&Wkh, g_Wkh);
    cudaGetSymbolAddress((void**)&Gt,  g_Gt);

    cudaFuncSetAttribute(gemm_gt,
                         cudaFuncAttributeMaxDynamicSharedMemorySize, SMEM_TOTAL);
    cudaFuncSetAttribute(k_p1b,
                         cudaFuncAttributeMaxDynamicSharedMemorySize, SMEM_TOTAL);
    cudaFuncSetAttribute(k_attn,
                         cudaFuncAttributeMaxDynamicSharedMemorySize, SMEM_TOTAL);

    const int MTOT = BATCH * SEQ;   // 16384

    // ---- prep ----
    k_prep_w<<<dim3(32, 32, 4), 256>>>(Wq, Wk, Wv, bq, bk);
    k_f2h_uw<<<MTOT, 256>>>((const float4*)x);

    // ---- Gt = Wk @ Wq^T ----
    launch_pdl(gemm_gt, dim3(8, 8, 1), dim3(128), SMEM_TOTAL,
               (const __half*)Wkh, (const __half*)Wqh, (__half*)Gt);

    // ---- mixed: T = x@G and V^T = Wvt@x^T + bv ----
    launch_pdl(k_p1b, dim3(128 + 64, 1, BATCH), dim3(128), SMEM_TOTAL, (const float*)bv);

    // ---- fused QKT + PV (ticketed ordering, PV spins on row counters) ----
    launch_pdl(k_attn, dim3(N_QKT + N_PV, 1, 1), dim3(128), SMEM_TOTAL, out);
}

// round 17
// speedup vs baseline: 1.4383x; 1.0580x over previous
#include <cuda_runtime.h>
#include <cuda_fp16.h>
#include <cstdint>

#define DINL __device__ __forceinline__

static constexpr int BATCH = 8;
static constexpr int SEQ   = 2048;
static constexpr int DIM   = 1024;
static constexpr int ODIM  = 512;

// ---------------- scratch (device globals; allocation-free) ----------------
__device__ __align__(1024) __half g_xh [(size_t)BATCH * SEQ * DIM];   // 32 MB
__device__ __align__(1024) __half g_Wqh[(size_t)DIM * DIM];           //  2 MB Wq fp16
__device__ __align__(1024) __half g_Wkh[(size_t)DIM * DIM];           //  2 MB Wk fp16
__device__ __align__(1024) __half g_Wvt[(size_t)ODIM * DIM];          //  1 MB Wv^T [o][k]
__device__ __align__(1024) __half g_Gt [(size_t)DIM * DIM];           //  2 MB G^T = Wk Wq^T
__device__ __align__(1024) __half g_Th [(size_t)BATCH * SEQ * DIM];   // 32 MB T = x@G
__device__ __align__(1024) __half g_Vth[(size_t)BATCH * ODIM * SEQ];  // 16 MB V^T per batch
__device__ __align__(1024) __half g_Ph [(size_t)BATCH * SEQ * SEQ];   // 64 MB exp-scores
__device__ __align__(1024) float  g_rsp[(size_t)BATCH * SEQ * 16];    //  1 MB rowsum partials
__device__ __align__(16)   float  g_vq [DIM];                         // Wq @ bk
__device__ __align__(16)   float  g_vk [DIM];                         // Wk @ bq
__device__ __align__(16)   float  g_u  [(size_t)BATCH * SEQ];         // SCALE * x.vq
__device__ __align__(16)   float  g_w  [(size_t)BATCH * SEQ];         // SCALE * (x.vk + c)
__device__ float    g_c;
__device__ unsigned g_ticket;                // job dispenser
__device__ unsigned g_gtc;                   // Gt tiles done (64 total)
__device__ unsigned g_vrdy[BATCH * 4];       // Vproj tiles done per (b, o-tile) (16 each)
__device__ unsigned g_trdy[BATCH * 16];      // Tproj tiles done per (b, row) (8 each)
__device__ unsigned g_rdy [BATCH * 16];      // QKT tiles done per (b, row)

// ------- GEMM config: CTA 128x128, 4 warps (2x2), warp 64x64, BK=64, 3 stages -------
static constexpr int BM = 128, BN = 128, BK = 64;
static constexpr int STR  = BK + 8;                 // 72 halves/row
static constexpr int TSTG = BM * STR;               // 9216 halves per tile stage
static constexpr int NSTG = 3;
static constexpr int EXT_OFF = NSTG * 2 * TSTG * 2; // 110592 B
static constexpr int SMEM_TOTAL = EXT_OFF + 2048;   // + f32 scratch (512 floats)

static constexpr float SCALE = 0.03125f;            // 1/sqrt(1024)

// job ranges
static constexpr unsigned J_GT = 64;                 // Gt tiles
static constexpr unsigned J_VP = J_GT + 512;         // + Vproj
static constexpr unsigned J_TP = J_VP + 1024;        // + Tproj
static constexpr unsigned J_QK = J_TP + 1088;        // + QKT
static constexpr unsigned J_PV = J_QK + 512;         // + PV  (= 3200 total)

DINL void cp_async16(uint32_t smem_addr, const void* gmem) {
    asm volatile("cp.async.cg.shared.global [%0], [%1], 16;\n" :: "r"(smem_addr), "l"(gmem));
}
DINL void cp_commit() { asm volatile("cp.async.commit_group;\n"); }
DINL void cp_wait1()  { asm volatile("cp.async.wait_group 1;\n"); }

DINL void ldsm4(uint32_t* r, uint32_t addr) {
    asm volatile("ldmatrix.sync.aligned.m8n8.x4.shared.b16 {%0,%1,%2,%3}, [%4];"
                 : "=r"(r[0]), "=r"(r[1]), "=r"(r[2]), "=r"(r[3]) : "r"(addr));
}
DINL void mma16816(float* c, const uint32_t* a, uint32_t b0, uint32_t b1) {
    asm volatile(
        "mma.sync.aligned.m16n8k16.row.col.f32.f16.f16.f32 "
        "{%0,%1,%2,%3}, {%4,%5,%6,%7}, {%8,%9}, {%0,%1,%2,%3};"
        : "+f"(c[0]), "+f"(c[1]), "+f"(c[2]), "+f"(c[3])
        : "r"(a[0]), "r"(a[1]), "r"(a[2]), "r"(a[3]), "r"(b0), "r"(b1));
}

DINL void pdl_wait()    { cudaGridDependencySynchronize(); }
DINL void pdl_trigger() { cudaTriggerProgrammaticLaunchCompletion(); }

// ---------------- shared mainloop (CTA 128x128, 4 warps 2x2, warp 64x64) ----------------
DINL void run_mainloop(const __half* __restrict__ A, const __half* __restrict__ B,
                       int lda, int ldb, int m0, int n0, int nT,
                       char* smraw, int tid, int wm, int wn, int lane, float (*acc)[8][4])
{
    __half* As = (__half*)smraw;
    __half* Bs = As + NSTG * TSTG;

    auto load = [&](int stage, int t) {
        __half* da = As + stage * TSTG;
        __half* db = Bs + stage * TSTG;
#pragma unroll
        for (int i = 0; i < 8; i++) {
            const int j = i * 128 + tid;
            const int r = j >> 3, c = (j & 7) << 3;
            cp_async16((uint32_t)__cvta_generic_to_shared(da + r * STR + c),
                       A + (long)(m0 + r) * lda + t * BK + c);
            cp_async16((uint32_t)__cvta_generic_to_shared(db + r * STR + c),
                       B + (long)(n0 + r) * ldb + t * BK + c);
        }
    };

    load(0, 0); cp_commit();
    load(1, 1); cp_commit();

    const uint32_t aB = (uint32_t)__cvta_generic_to_shared(As) +
        ((((wm * 64 + (lane & 15)) * STR) + ((lane >> 4) << 3)) << 1);
    const uint32_t bB = (uint32_t)__cvta_generic_to_shared(Bs) +
        ((((wn * 64 + (lane & 15)) * STR) + ((lane >> 4) << 3)) << 1);

    uint32_t a[2][4][4], b[2][4][4];
    int st = 0;
    for (int t = 0; t < nT; t++) {
        cp_wait1();
        __syncthreads();
        if (t + 2 < nT) load(st == 0 ? 2 : st - 1, t + 2);
        cp_commit();

        const uint32_t aS = aB + st * (TSTG * 2);
        const uint32_t bS = bB + st * (TSTG * 2);

#pragma unroll
        for (int mt = 0; mt < 4; mt++) ldsm4(a[0][mt], aS + mt * (16 * STR * 2));
#pragma unroll
        for (int gb = 0; gb < 4; gb++) ldsm4(b[0][gb], bS + gb * (16 * STR * 2));

#pragma unroll
        for (int ks = 0; ks < 4; ks++) {
            const int cur = ks & 1, nxt = cur ^ 1;
            if (ks < 3) {
#pragma unroll
                for (int mt = 0; mt < 4; mt++)
                    ldsm4(a[nxt][mt], aS + mt * (16 * STR * 2) + (ks + 1) * 32);
#pragma unroll
                for (int gb = 0; gb < 4; gb++)
                    ldsm4(b[nxt][gb], bS + gb * (16 * STR * 2) + (ks + 1) * 32);
            }
#pragma unroll
            for (int mt = 0; mt < 4; mt++)
#pragma unroll
                for (int nt = 0; nt < 8; nt++)
                    mma16816(acc[mt][nt], a[cur][mt],
                             b[cur][nt >> 1][nt & 1], b[cur][nt >> 1][(nt & 1) + 2]);
        }
        st = (st == 2) ? 0 : st + 1;
    }
    __syncthreads();
}

DINL void spin_until(unsigned* ctr, unsigned target, int tid)
{
    if (tid == 0) {
        while (atomicAdd(ctr, 0u) < target) __nanosleep(128);
    }
    __syncthreads();
}

// =====================================================================
// Mega kernel: the whole GEMM DAG, ticket-ordered with dependency counters.
//   [0,64)      Gt   = Wk @ Wq^T
//   [64,576)    Vproj: V^T = Wvt @ x^T + bv
//   [576,1600)  Tproj: T = x @ G            (waits: all Gt)
//   [1600,2688) QKT:  Ph = exp(..)          (waits: Tproj row)
//   [2688,3200) PV:   out = Ph@Vth^T / rs   (waits: QKT row + Vproj o-tile)
// =====================================================================
__global__ __launch_bounds__(128, 2) void k_mega(const float* __restrict__ bv,
                                                 float* __restrict__ out)
{
    pdl_wait();

    __shared__ unsigned sjob;
    const int tid = threadIdx.x, warp = tid >> 5, lane = tid & 31;
    const int wm = warp >> 1, wn = warp & 1;
    if (tid == 0) sjob = atomicAdd(&g_ticket, 1u);
    __syncthreads();
    const unsigned job = sjob;

    extern __shared__ __align__(16) char smraw[];
    float* sext = (float*)(smraw + EXT_OFF);   // [0..255] reduce, [256..383] u, [384..511] w

    float acc[4][8][4];
#pragma unroll
    for (int i = 0; i < 4; i++)
#pragma unroll
        for (int j = 0; j < 8; j++)
#pragma unroll
            for (int k = 0; k < 4; k++) acc[i][j][k] = 0.f;

    const int g = lane >> 2, cth = lane & 3;

    if (job < J_TP) {
        // ---------------- plain GEMM path: Gt / Vproj / Tproj ----------------
        const __half *A, *B;
        __half* C;
        int lda, ldb, ldc, m0, n0;
        bool addb = false;
        unsigned* ctr;

        if (job < J_GT) {                       // Gt tile
            m0 = (int)(job >> 3) * BM;
            n0 = (int)(job & 7) * BN;
            A = g_Wkh; lda = DIM;
            B = g_Wqh; ldb = DIM;
            C = g_Gt;  ldc = DIM;
            ctr = &g_gtc;
        } else if (job < J_VP) {                // Vproj tile
            const unsigned j = job - J_GT;
            const int bz = j & 7, j2 = (int)(j >> 3);
            const int bx = j2 & 15, by = j2 >> 4;   // by in 0..3 (o-tile)
            m0 = by * BM; n0 = bx * BN;
            A = g_Wvt;                         lda = DIM;
            B = g_xh + (long)bz * SEQ * DIM;   ldb = DIM;
            C = g_Vth + (long)bz * ODIM * SEQ; ldc = SEQ;
            addb = true;
            ctr = &g_vrdy[bz * 4 + by];
        } else {                                // Tproj tile (waits for Gt)
            const unsigned j = job - J_VP;
            const int bz = j & 7, j2 = (int)(j >> 3);
            const int by = 15 - (j2 >> 3), bx = j2 & 7;   // heavy rows first
            m0 = by * BM; n0 = bx * BN;
            A = g_xh + (long)bz * SEQ * DIM; lda = DIM;
            B = g_Gt;                        ldb = DIM;
            C = g_Th + (long)bz * SEQ * DIM; ldc = DIM;
            ctr = &g_trdy[bz * 16 + by];
            spin_until(&g_gtc, 64u, tid);
        }

        run_mainloop(A, B, lda, ldb, m0, n0, DIM / BK, smraw, tid, wm, wn, lane, acc);

#pragma unroll
        for (int mt = 0; mt < 4; mt++) {
            const int rr = m0 + wm * 64 + mt * 16 + g;
            float rb0 = 0.f, rb1 = 0.f;
            if (addb) { rb0 = __ldg(bv + rr); rb1 = __ldg(bv + rr + 8); }
#pragma unroll
            for (int nt = 0; nt < 8; nt++) {
                const int cc = n0 + wn * 64 + nt * 8 + (cth << 1);
                *(__half2*)(C + (long)rr * ldc + cc) =
                    __floats2half2_rn(acc[mt][nt][0] + rb0, acc[mt][nt][1] + rb0);
                *(__half2*)(C + (long)(rr + 8) * ldc + cc) =
                    __floats2half2_rn(acc[mt][nt][2] + rb1, acc[mt][nt][3] + rb1);
            }
        }
        __threadfence();
        __syncthreads();
        if (tid == 0) atomicAdd(ctr, 1u);
    } else if (job < J_QK) {
        // ---------------- QKT job ----------------
        const unsigned j = job - J_TP;
        const int bz = j & 7;
        const int i  = 135 - (int)(j >> 3);     // descending row order
        int r = (int)((sqrtf(8.f * i + 1.f) - 1.f) * 0.5f);
        while ((r + 1) * (r + 2) / 2 <= i) r++;
        while (r * (r + 1) / 2 > i) r--;
        const int by = r, bx = i - r * (r + 1) / 2;
        const int m0 = by * BM, n0 = bx * BN;

        const __half* A = g_Th + (long)bz * SEQ * DIM;
        const __half* B = g_xh + (long)bz * SEQ * DIM;
        __half* C = g_Ph + (long)bz * SEQ * SEQ;

        sext[256 + tid] = __ldg(g_u + (long)bz * SEQ + m0 + tid);
        sext[384 + tid] = __ldg(g_w + (long)bz * SEQ + n0 + tid);

        spin_until(&g_trdy[bz * 16 + by], 8u, tid);   // T row ready

        run_mainloop(A, B, DIM, DIM, m0, n0, DIM / BK, smraw, tid, wm, wn, lane, acc);

        float rsum[8];
#pragma unroll
        for (int ii = 0; ii < 8; ii++) rsum[ii] = 0.f;

#pragma unroll
        for (int mt = 0; mt < 4; mt++) {
            const int lr = wm * 64 + mt * 16 + g;
            const int rr = m0 + lr;
            const float u0 = sext[256 + lr], u1 = sext[256 + lr + 8];
#pragma unroll
            for (int nt = 0; nt < 8; nt++) {
                const int lc = wn * 64 + nt * 8 + (cth << 1);
                const int cc = n0 + lc;
                const float w0 = sext[384 + lc], w1 = sext[384 + lc + 1];
                float v00 = (cc     <= rr    ) ? __expf(fmaf(acc[mt][nt][0], SCALE, u0 + w0)) : 0.f;
                float v01 = (cc + 1 <= rr    ) ? __expf(fmaf(acc[mt][nt][1], SCALE, u0 + w1)) : 0.f;
                float v10 = (cc     <= rr + 8) ? __expf(fmaf(acc[mt][nt][2], SCALE, u1 + w0)) : 0.f;
                float v11 = (cc + 1 <= rr + 8) ? __expf(fmaf(acc[mt][nt][3], SCALE, u1 + w1)) : 0.f;
                rsum[mt * 2]     += v00 + v01;
                rsum[mt * 2 + 1] += v10 + v11;
                *(__half2*)(C + (long)rr * SEQ + cc)       = __floats2half2_rn(v00, v01);
                *(__half2*)(C + (long)(rr + 8) * SEQ + cc) = __floats2half2_rn(v10, v11);
            }
        }

#pragma unroll
        for (int ii = 0; ii < 8; ii++) {
            rsum[ii] += __shfl_xor_sync(0xffffffffu, rsum[ii], 1);
            rsum[ii] += __shfl_xor_sync(0xffffffffu, rsum[ii], 2);
        }
        if (cth == 0) {
#pragma unroll
            for (int mt = 0; mt < 4; mt++) {
                sext[wn * BM + wm * 64 + mt * 16 + g]     = rsum[mt * 2];
                sext[wn * BM + wm * 64 + mt * 16 + g + 8] = rsum[mt * 2 + 1];
            }
        }
        __syncthreads();
        g_rsp[((long)bz * SEQ + m0 + tid) * 16 + bx] = sext[tid] + sext[BM + tid];

        __threadfence();
        __syncthreads();
        if (tid == 0) atomicAdd(&g_rdy[bz * 16 + by], 1u);
    } else {
        // ---------------- PV job ----------------
        const unsigned j = job - J_QK;
        const int bz = j & 7;
        const int j2 = (int)(j >> 3);             // 0..63
        const int by = 15 - (j2 >> 2);            // heavy rows first
        const int ox = j2 & 3;
        const int m0 = by * BM, n0 = ox * BN;
        const int nT = (by + 1) * 2;              // (by+1)*128 / BK

        // wait: QKT row complete + Vproj o-tile complete
        if (tid == 0) {
            while (atomicAdd(&g_rdy[bz * 16 + by], 0u) < (unsigned)(by + 1)) __nanosleep(128);
            while (atomicAdd(&g_vrdy[bz * 4 + ox], 0u) < 16u) __nanosleep(128);
        }
        __syncthreads();

        const float* rp = g_rsp + ((long)bz * SEQ + m0 + tid) * 16;
        float s = 0.f;
        for (int p = 0; p <= by; p++) s += __ldcg(rp + p);
        sext[tid] = 1.f / s;
        __syncthreads();

        const __half* A = g_Ph + (long)bz * SEQ * SEQ;
        const __half* B = g_Vth + (long)bz * ODIM * SEQ;
        float* C = out + (long)bz * SEQ * ODIM;

        run_mainloop(A, B, SEQ, SEQ, m0, n0, nT, smraw, tid, wm, wn, lane, acc);

#pragma unroll
        for (int mt = 0; mt < 4; mt++) {
            const int lr = wm * 64 + mt * 16 + g;
            const int rr = m0 + lr;
            const float inv0 = sext[lr], inv1 = sext[lr + 8];
#pragma unroll
            for (int nt = 0; nt < 8; nt++) {
                const int cc = n0 + wn * 64 + nt * 8 + (cth << 1);
                *(float2*)(C + (long)rr * ODIM + cc) =
                    make_float2(acc[mt][nt][0] * inv0, acc[mt][nt][1] * inv0);
                *(float2*)(C + (long)(rr + 8) * ODIM + cc) =
                    make_float2(acc[mt][nt][2] * inv1, acc[mt][nt][3] * inv1);
            }
        }
    }
}

// =====================================================================
// Prep 1: Wq/Wk convert, Wv^T transpose, vq/vk/c, scheduler state reset.
// =====================================================================
__global__ __launch_bounds__(256) void k_prep_w(
    const float* __restrict__ Wq, const float* __restrict__ Wk,
    const float* __restrict__ Wv, const float* __restrict__ bq,
    const float* __restrict__ bk)
{
    const int z = blockIdx.z;
    const int tid = threadIdx.x;
    const int bid = blockIdx.y * 32 + blockIdx.x;

    if (z == 0 || z == 1) {        // straight convert
        const float* W = (z == 0) ? Wq : Wk;
        __half2* dst = (__half2*)((z == 0) ? g_Wqh : g_Wkh);
        const float4 v = ((const float4*)W)[bid * 256 + tid];
        dst[bid * 512 + tid * 2]     = __floats2half2_rn(v.x, v.y);
        dst[bid * 512 + tid * 2 + 1] = __floats2half2_rn(v.z, v.w);
        return;
    }
    if (z == 2) {
        if (blockIdx.x < 16) {      // Wv transpose
            __shared__ float t[32][33];
            const int n0 = blockIdx.x * 32, k0 = blockIdx.y * 32;
            const int x = tid & 31, y = tid >> 5;
#pragma unroll
            for (int rr = 0; rr < 32; rr += 8)
                t[y + rr][x] = Wv[(long)(k0 + y + rr) * ODIM + n0 + x];
            __syncthreads();
#pragma unroll
            for (int rr = 0; rr < 32; rr += 8)
                g_Wvt[(long)(n0 + y + rr) * DIM + k0 + x] = __float2half(t[x][y + rr]);
        } else if (blockIdx.x == 16 && blockIdx.y == 0) {   // c = bq.bk
            float s = 0.f;
            for (int e = tid; e < DIM; e += 256) s += bq[e] * bk[e];
#pragma unroll
            for (int o = 16; o; o >>= 1) s += __shfl_xor_sync(0xffffffffu, s, o);
            __shared__ float red[8];
            if ((tid & 31) == 0) red[tid >> 5] = s;
            __syncthreads();
            if (tid == 0) {
                float c = 0.f;
                for (int ii = 0; ii < 8; ii++) c += red[ii];
                g_c = c;
            }
        } else if (blockIdx.x == 17 && blockIdx.y == 0) {   // reset scheduler state
            if (tid == 0) { g_ticket = 0; g_gtc = 0; }
            if (tid < BATCH * 16) { g_trdy[tid] = 0; g_rdy[tid] = 0; }
            if (tid < BATCH * 4)  g_vrdy[tid] = 0;
        }
        return;
    }
    // z == 3: vq rows (bid<128) / vk rows (128<=bid<256), one warp per row
    if (bid >= 256) return;
    const int w = tid >> 5, lane = tid & 31;
    const bool isq = bid < 128;
    const int row = (isq ? bid : bid - 128) * 8 + w;
    const float* R = (isq ? Wq : Wk) + (long)row * DIM;
    const float* bvv = isq ? bk : bq;
    float s = 0.f;
    for (int e = lane; e < DIM; e += 32) s += R[e] * bvv[e];
#pragma unroll
    for (int o = 16; o; o >>= 1) s += __shfl_xor_sync(0xffffffffu, s, o);
    if (lane == 0) { if (isq) g_vq[row] = s; else g_vk[row] = s; }
}

// =====================================================================
// Prep 2: x -> fp16, and u/w row dots (one block per row of x).
// =====================================================================
__global__ __launch_bounds__(256) void k_f2h_uw(const float4* __restrict__ x4)
{
    const long row = blockIdx.x;
    const int tid = threadIdx.x;
    const float4 v = x4[row * 256 + tid];
    __half2* dst = (__half2*)g_xh + row * 512 + tid * 2;
    dst[0] = __floats2half2_rn(v.x, v.y);
    dst[1] = __floats2half2_rn(v.z, v.w);

    const float4 q4 = *(const float4*)(g_vq + tid * 4);
    const float4 k4 = *(const float4*)(g_vk + tid * 4);
    float du = v.x * q4.x + v.y * q4.y + v.z * q4.z + v.w * q4.w;
    float dw = v.x * k4.x + v.y * k4.y + v.z * k4.z + v.w * k4.w;
#pragma unroll
    for (int o = 16; o; o >>= 1) {
        du += __shfl_xor_sync(0xffffffffu, du, o);
        dw += __shfl_xor_sync(0xffffffffu, dw, o);
    }
    __shared__ float ru[8], rw[8];
    if ((tid & 31) == 0) { ru[tid >> 5] = du; rw[tid >> 5] = dw; }
    __syncthreads();
    if (tid == 0) {
        float su = 0.f, sw = 0.f;
#pragma unroll
        for (int ii = 0; ii < 8; ii++) { su += ru[ii]; sw += rw[ii]; }
        g_u[row] = SCALE * su;
        g_w[row] = SCALE * (sw + g_c);
    }
}

// ---------------- host side ----------------
template <typename K, typename... Args>
static void launch_pdl(K kern, dim3 grid, dim3 block, int smem, Args... args)
{
    cudaLaunchConfig_t cfg = {};
    cfg.gridDim = grid;
    cfg.blockDim = block;
    cfg.dynamicSmemBytes = (size_t)smem;
    cfg.stream = 0;
    cudaLaunchAttribute at[1];
    at[0].id = cudaLaunchAttributeProgrammaticStreamSerialization;
    at[0].val.programmaticStreamSerializationAllowed = 1;
    cfg.attrs = at;
    cfg.numAttrs = 1;
    cudaLaunchKernelEx(&cfg, kern, args...);
}

extern "C" void kernel_launch(void* const* d_in, const int* in_sizes, int n_in,
                              void* d_out, int out_size)
{
    (void)in_sizes; (void)n_in; (void)out_size;
    const float* x  = (const float*)d_in[0];
    const float* Wq = (const float*)d_in[1];
    const float* bq = (const float*)d_in[2];
    const float* Wk = (const float*)d_in[3];
    const float* bk = (const float*)d_in[4];
    const float* Wv = (const float*)d_in[5];
    const float* bv = (const float*)d_in[6];
    float* out = (float*)d_out;

    cudaFuncSetAttribute(k_mega,
                         cudaFuncAttributeMaxDynamicSharedMemorySize, SMEM_TOTAL);

    const int MTOT = BATCH * SEQ;   // 16384

    // ---- prep ----
    k_prep_w<<<dim3(32, 32, 4), 256>>>(Wq, Wk, Wv, bq, bk);
    k_f2h_uw<<<MTOT, 256>>>((const float4*)x);

    // ---- the whole GEMM DAG, one ticketed launch ----
    launch_pdl(k_mega, dim3(J_PV, 1, 1), dim3(128), SMEM_TOTAL, (const float*)bv, out);
}